// round 3
// baseline (speedup 1.0000x reference)
#include <cuda_runtime.h>
#include <math.h>

#define NB   4
#define NPT  4096
#define NS   4096
#define CIND 128
#define DIMD 64
#define KNNK 20
#define MTOT (NB*NPT*KNNK)   /* 327680 */
#define PTOT (NB*NPT)        /* 16384  */
#define MT   80              /* m-rows per CTA in fused attn kernel (4 points) */

// ---------------- static device scratch (no runtime allocation) ----------------
__device__ float g_q[PTOT*DIMD];
__device__ float g_k[PTOT*DIMD];
__device__ float g_v[PTOT*DIMD];
__device__ int   g_idx[PTOT*KNNK];
__device__ float g_h [MTOT*DIMD];     // [m][d]
__device__ float g_vg[MTOT*DIMD];     // [m][d]
__device__ float g_agg[PTOT*2*DIMD];  // [q][d], q = point*2+r
__device__ float g_aw1t[64*256];      // [d][c]   transposed aw1
__device__ float g_w2t[256*128];      // [c][r*64+o]  permuted awt
__device__ float g_wet[64*128];       // [d][o2]  transposed we
__device__ float g_abn[512];          // [0:256) inv, [256:512) fused bias

// ---------------- packed f32x2 helpers (FFMA2: 2 MACs per fma-pipe issue) ----
__device__ __forceinline__ unsigned long long ffma2(unsigned long long a,
                                                    unsigned long long b,
                                                    unsigned long long c) {
    unsigned long long d;
    asm("fma.rn.f32x2 %0, %1, %2, %3;" : "=l"(d) : "l"(a), "l"(b), "l"(c));
    return d;
}
__device__ __forceinline__ unsigned long long pack2(float lo, float hi) {
    unsigned long long d;
    asm("mov.b64 %0, {%1, %2};" : "=l"(d) : "f"(lo), "f"(hi));
    return d;
}
__device__ __forceinline__ float2 unpack2(unsigned long long v) {
    float2 r;
    asm("mov.b64 {%0, %1}, %2;" : "=f"(r.x), "=f"(r.y) : "l"(v));
    return r;
}

// ============================================================================
// Setup: transpose/permute weights, fold BN constants. One-shot, tiny.
// ============================================================================
__global__ void setup_kernel(const float* __restrict__ aw1, const float* __restrict__ awt,
                             const float* __restrict__ we,  const float* __restrict__ ag,
                             const float* __restrict__ av,  const float* __restrict__ ab1,
                             const float* __restrict__ am,  const float* __restrict__ abt2)
{
    int i0 = blockIdx.x*256 + threadIdx.x;
    int stride = gridDim.x*256;
    for (int i=i0; i<64*256; i+=stride) { int d=i>>8, c=i&255; g_aw1t[i] = aw1[c*64+d]; }
    for (int i=i0; i<256*128; i+=stride) {
        int c=i>>7, oo=i&127; int r=oo>>6, o=oo&63;
        g_w2t[i] = awt[c*128 + o*2 + r];
    }
    for (int i=i0; i<64*128; i+=stride) { int d=i>>7, o2=i&127; g_wet[i] = we[o2*64+d]; }
    for (int i=i0; i<256; i+=stride) {
        float inv = ag[i]*rsqrtf(av[i]+1e-5f);
        g_abn[i]     = inv;
        g_abn[256+i] = (ab1[i]-am[i])*inv + abt2[i];
    }
}

// ============================================================================
// Kernel 1: q/k/v 1x1 conv.
// ============================================================================
__global__ __launch_bounds__(256) void qkv_kernel(
    const float* __restrict__ query, const float* __restrict__ key_feat,
    const float* __restrict__ wq, const float* __restrict__ bq,
    const float* __restrict__ wk, const float* __restrict__ bk,
    const float* __restrict__ wv, const float* __restrict__ bv)
{
    __shared__ float Wsm[64*129];
    __shared__ __align__(16) float xs[128*16];
    int t = threadIdx.x;
    int z = blockIdx.z;
    const float* W    = (z==0)? wq : (z==1)? wk : wv;
    const float* bias = (z==0)? bq : (z==1)? bk : bv;
    const float* inp  = (z==0)? query : key_feat;
    float* outp       = (z==0)? g_q : (z==1)? g_k : g_v;
    int b  = blockIdx.y;
    int n0 = blockIdx.x * 16;

    for (int idx=t; idx<64*128; idx+=256) Wsm[(idx>>7)*129 + (idx&127)] = W[idx];
    for (int idx=t; idx<128*16; idx+=256) {
        int c = idx>>4, i = idx&15;
        xs[c*16+i] = inp[(b*CIND+c)*NPT + n0 + i];
    }
    __syncthreads();

    int d = t & 63, g = t >> 6;
    float bb = bias[d];
    float acc0=bb, acc1=bb, acc2=bb, acc3=bb;
    for (int c=0; c<128; ++c) {
        float w = Wsm[d*129+c];
        float4 v4 = *(const float4*)&xs[c*16 + g*4];
        acc0 += w*v4.x; acc1 += w*v4.y; acc2 += w*v4.z; acc3 += w*v4.w;
    }
    int pb = (b*NPT + n0 + g*4);
    outp[(pb+0)*DIMD + d] = acc0;
    outp[(pb+1)*DIMD + d] = acc1;
    outp[(pb+2)*DIMD + d] = acc2;
    outp[(pb+3)*DIMD + d] = acc3;
}

// ============================================================================
// Kernel 2: KNN (top-20 smallest d = |p1|^2+|p2|^2-2 p1.p2, stable ties).
// ============================================================================
__global__ __launch_bounds__(128) void knn_kernel(
    const float* __restrict__ pos1, const float* __restrict__ pos2)
{
    __shared__ float4 sp[2048];
    int t = threadIdx.x;
    int b = blockIdx.y;
    int n = blockIdx.x*128 + t;
    const float* p1 = pos1 + b*3*NPT;
    float qx = p1[n], qy = p1[NPT+n], qz = p1[2*NPT+n];
    float s1 = qx*qx + qy*qy + qz*qz;

    float bd[KNNK]; int bi[KNNK];
    #pragma unroll
    for (int i=0;i<KNNK;++i) { bd[i]=1e30f; bi[i]=0; }

    const float* p2 = pos2 + b*3*NS;
    for (int ch=0; ch<2; ++ch) {
        __syncthreads();
        for (int j=t; j<2048; j+=128) {
            int jg = ch*2048 + j;
            float x=p2[jg], y=p2[NS+jg], z=p2[2*NS+jg];
            sp[j] = make_float4(x, y, z, x*x+y*y+z*z);
        }
        __syncthreads();
        for (int j=0; j<2048; ++j) {
            float4 p = sp[j];
            float dd = s1 + p.w - 2.0f*(qx*p.x + qy*p.y + qz*p.z);
            if (dd < bd[KNNK-1]) {
                int jg = ch*2048 + j;
                #pragma unroll
                for (int i=KNNK-1; i>=1; --i) {
                    if (dd < bd[i]) {
                        bool sh = dd < bd[i-1];
                        bd[i] = sh ? bd[i-1] : dd;
                        bi[i] = sh ? bi[i-1] : jg;
                    }
                }
                if (dd < bd[0]) { bd[0]=dd; bi[0]=jg; }
            }
        }
    }
    int* op = &g_idx[(b*NPT + n)*KNNK];
    #pragma unroll
    for (int i=0;i<KNNK;++i) op[i] = bi[i];
}

// ============================================================================
// Kernel 3: gather + pos-MLP; h = q - k_g + pe ; vg = v_g + pe
// ============================================================================
__global__ __launch_bounds__(128) void prep_kernel(
    const float* __restrict__ pos1, const float* __restrict__ pos2,
    const float* __restrict__ pw1, const float* __restrict__ pb1,
    const float* __restrict__ pg,  const float* __restrict__ pbt,
    const float* __restrict__ pm,  const float* __restrict__ pvv,
    const float* __restrict__ pw2, const float* __restrict__ pb2)
{
    __shared__ float pw2s[64*65];
    __shared__ __align__(16) float pe1s[2][64*24];
    __shared__ float prel[2][3][KNNK];
    __shared__ float qs[2][64];
    __shared__ int idxs[2][KNNK];
    int t = threadIdx.x;
    int p0 = blockIdx.x*2;

    for (int idx=t; idx<64*64; idx+=128) pw2s[(idx>>6)*65 + (idx&63)] = pw2[idx];
    if (t < 2*KNNK) idxs[t/KNNK][t%KNNK] = g_idx[p0*KNNK + t];
    {
        int pp = t>>6, d = t&63;
        qs[pp][d] = g_q[(p0+pp)*DIMD + d];
    }
    __syncthreads();

    if (t < 2*3*KNNK) {
        int pp = t/(3*KNNK), r = t%(3*KNNK);
        int c = r/KNNK, k = r%KNNK;
        int p = p0+pp, b = p>>12, n = p&4095;
        prel[pp][c][k] = pos1[(b*3+c)*NPT + n] - pos2[(b*3+c)*NS + idxs[pp][k]];
    }
    __syncthreads();

    {   // pe1 = relu(bn(pw1 @ pos_rel + pb1))
        int cH = t & 63, pp = t >> 6;
        float w0 = pw1[cH*3], w1 = pw1[cH*3+1], w2v = pw1[cH*3+2];
        float inv = pg[cH]*rsqrtf(pvv[cH]+1e-5f);
        float tb  = (pb1[cH]-pm[cH])*inv + pbt[cH];
        #pragma unroll
        for (int k=0;k<KNNK;++k) {
            float s = w0*prel[pp][0][k] + w1*prel[pp][1][k] + w2v*prel[pp][2][k];
            pe1s[pp][cH*24+k] = fmaxf(s*inv + tb, 0.0f);
        }
    }
    __syncthreads();

    {   // pe = pw2 @ pe1 + pb2 ; emit h, vg
        int d = t&63, pp = t>>6;
        int p = p0+pp, b = p>>12;
        float acc[KNNK]; float bias = pb2[d];
        #pragma unroll
        for (int k=0;k<KNNK;++k) acc[k]=bias;
        for (int cH=0;cH<64;++cH) {
            float w = pw2s[d*65+cH];
            #pragma unroll
            for (int k4=0;k4<5;++k4) {
                float4 v4 = *(const float4*)&pe1s[pp][cH*24 + k4*4];
                acc[k4*4+0]+=w*v4.x; acc[k4*4+1]+=w*v4.y;
                acc[k4*4+2]+=w*v4.z; acc[k4*4+3]+=w*v4.w;
            }
        }
        float qv = qs[pp][d];
        #pragma unroll
        for (int k=0;k<KNNK;++k) {
            int j = idxs[pp][k];
            int m = p*KNNK + k;
            float kg = g_k[(b*NS+j)*DIMD + d];
            float vv = g_v[(b*NS+j)*DIMD + d];
            g_h [m*DIMD + d] = qv - kg + acc[k];
            g_vg[m*DIMD + d] = vv + acc[k];
        }
    }
}

// ============================================================================
// Kernel 4 (FUSED): gemm1 + BN/ReLU + gemm2 + softmax + aggregation.
// 80 m-rows (4 whole points) per CTA, block 320 (10 warps, 8 m-rows each).
// Packed f32x2 FMA throughout; intra-warp gemm1->gemm2 handoff (syncwarp only).
// Dynamic smem: ast 256x84 | hst 64x84 | ls 128x84 | vgs 80x64 = 171008 B.
// ============================================================================
#define SM_AST 0
#define SM_HST 21504
#define SM_LS  26880
#define SM_VGS 37632
#define SM_FLOATS 42752

__global__ __launch_bounds__(320) void attn_kernel()
{
    extern __shared__ __align__(16) float sm[];
    float* ast = sm + SM_AST;   // [c=256][m=80] pad 84
    float* hst = sm + SM_HST;   // [d=64][m=80] pad 84
    float* ls  = sm + SM_LS;    // [o'=128][m=80] pad 84
    float* vgs = sm + SM_VGS;   // [m=80][d=64]
    int t = threadIdx.x;
    int w = t >> 5, cg = t & 31;
    int m0 = blockIdx.x * MT;

    // ---- load h, transposed into hst[d][m] ----
    for (int idx = t; idx < MT*64; idx += 320) {
        int m = idx >> 6, d = idx & 63;
        hst[d*84 + m] = g_h[(m0+m)*64 + d];
    }
    __syncthreads();

    // ---- phase 1: a[c][m] = relu(bn(aw1t . h)), K=64 ----
    unsigned long long acc1[8][4];
    #pragma unroll
    for (int j=0;j<8;++j)
        #pragma unroll
        for (int mp=0;mp<4;++mp) acc1[j][mp] = 0ull;

    for (int d=0; d<64; ++d) {
        ulonglong2 u0 = *(const ulonglong2*)&hst[d*84 + w*8];
        ulonglong2 u1 = *(const ulonglong2*)&hst[d*84 + w*8 + 4];
        unsigned long long hv0=u0.x, hv1=u0.y, hv2=u1.x, hv3=u1.y;
        const float* wr = &g_aw1t[d*256 + cg];
        #pragma unroll
        for (int j=0;j<8;++j) {
            float wv = __ldg(&wr[32*j]);
            unsigned long long wp = pack2(wv, wv);
            acc1[j][0] = ffma2(wp, hv0, acc1[j][0]);
            acc1[j][1] = ffma2(wp, hv1, acc1[j][1]);
            acc1[j][2] = ffma2(wp, hv2, acc1[j][2]);
            acc1[j][3] = ffma2(wp, hv3, acc1[j][3]);
        }
    }
    #pragma unroll
    for (int j=0;j<8;++j) {
        int c = cg + 32*j;
        float inv = g_abn[c], tb = g_abn[256+c];
        #pragma unroll
        for (int mp=0;mp<4;++mp) {
            float2 v = unpack2(acc1[j][mp]);
            v.x = fmaxf(fmaf(v.x, inv, tb), 0.f);
            v.y = fmaxf(fmaf(v.y, inv, tb), 0.f);
            *(float2*)&ast[c*84 + w*8 + 2*mp] = v;
        }
    }
    __syncwarp();

    // ---- phase 2: logits[o'][m] = w2t . a, K=256 ----
    unsigned long long acc2[4][4];
    #pragma unroll
    for (int j=0;j<4;++j)
        #pragma unroll
        for (int mp=0;mp<4;++mp) acc2[j][mp] = 0ull;

    for (int cc=0; cc<256; ++cc) {
        ulonglong2 u0 = *(const ulonglong2*)&ast[cc*84 + w*8];
        ulonglong2 u1 = *(const ulonglong2*)&ast[cc*84 + w*8 + 4];
        unsigned long long av0=u0.x, av1=u0.y, av2=u1.x, av3=u1.y;
        const float* wr = &g_w2t[cc*128 + cg];
        #pragma unroll
        for (int j=0;j<4;++j) {
            float wv = __ldg(&wr[32*j]);
            unsigned long long wp = pack2(wv, wv);
            acc2[j][0] = ffma2(wp, av0, acc2[j][0]);
            acc2[j][1] = ffma2(wp, av1, acc2[j][1]);
            acc2[j][2] = ffma2(wp, av2, acc2[j][2]);
            acc2[j][3] = ffma2(wp, av3, acc2[j][3]);
        }
    }
    #pragma unroll
    for (int j=0;j<4;++j) {
        int o = cg + 32*j;
        #pragma unroll
        for (int mp=0;mp<4;++mp)
            *(unsigned long long*)&ls[o*84 + w*8 + 2*mp] = acc2[j][mp];
    }

    // ---- load vg tile ----
    for (int idx = t; idx < MT*64; idx += 320)
        vgs[idx] = g_vg[m0*64 + idx];
    __syncthreads();

    // ---- phase 3: softmax over k (=20) + aggregation ----
    for (int idx = t; idx < 4*128; idx += 320) {
        int pp = idx >> 7, chn = idx & 127;
        int d = chn & 63;
        const float* lp = &ls[chn*84 + pp*KNNK];
        float lg[KNNK];
        #pragma unroll
        for (int k=0;k<KNNK;++k) lg[k] = lp[k];
        float mx = lg[0];
        #pragma unroll
        for (int k=1;k<KNNK;++k) mx = fmaxf(mx, lg[k]);
        float s = 0.f;
        #pragma unroll
        for (int k=0;k<KNNK;++k) { lg[k] = __expf(lg[k]-mx); s += lg[k]; }
        float inv = 1.f/s;
        const float* vp = &vgs[pp*KNNK*64 + d];
        float acc = 0.f;
        #pragma unroll
        for (int k=0;k<KNNK;++k) acc += lg[k]*vp[k*64];
        g_agg[(blockIdx.x*4 + pp)*128 + chn] = acc*inv;
    }
}

// ============================================================================
// Kernel 5: final 1x1 conv (DIM->CIN) + residual (nearest-upsampled query).
// ============================================================================
__global__ __launch_bounds__(256) void final_kernel(
    const float* __restrict__ query, const float* __restrict__ be,
    float* __restrict__ out)
{
    __shared__ float wes[64*128];
    __shared__ __align__(16) float aggt[64*16];
    int t = threadIdx.x;
    int q0 = blockIdx.x*16;
    for (int idx=t; idx<64*128; idx+=256) wes[idx] = g_wet[idx];
    for (int idx=t; idx<16*64; idx+=256) {
        int li = idx>>6, d = idx&63;
        aggt[d*16+li] = g_agg[(q0+li)*64 + d];
    }
    __syncthreads();

    int o2 = t & 127, h = t >> 7;
    float acc[8];
    #pragma unroll
    for (int i=0;i<8;++i) acc[i]=0.f;
    for (int d=0; d<64; ++d) {
        float w = wes[d*128+o2];
        float4 a0 = *(const float4*)&aggt[d*16 + h*8];
        float4 a1 = *(const float4*)&aggt[d*16 + h*8 + 4];
        acc[0]+=w*a0.x; acc[1]+=w*a0.y; acc[2]+=w*a0.z; acc[3]+=w*a0.w;
        acc[4]+=w*a1.x; acc[5]+=w*a1.y; acc[6]+=w*a1.z; acc[7]+=w*a1.w;
    }
    float bb = be[o2];
    #pragma unroll
    for (int i=0;i<8;++i) {
        int qq = q0 + h*8 + i;
        int b = qq >> 13, nr = qq & 8191, n = nr >> 1;
        out[b*(128*8192) + o2*8192 + nr] = acc[i] + bb
            + query[b*(128*4096) + o2*4096 + n];
    }
}

// ============================================================================
extern "C" void kernel_launch(void* const* d_in, const int* in_sizes, int n_in,
                              void* d_out, int out_size)
{
    const float* pos1     = (const float*)d_in[0];
    const float* query    = (const float*)d_in[1];
    const float* pos2     = (const float*)d_in[2];
    const float* key_feat = (const float*)d_in[3];
    const float* wq  = (const float*)d_in[4];
    const float* bq  = (const float*)d_in[5];
    const float* wk  = (const float*)d_in[6];
    const float* bk  = (const float*)d_in[7];
    const float* wv  = (const float*)d_in[8];
    const float* bv  = (const float*)d_in[9];
    const float* pw1 = (const float*)d_in[10];
    const float* pb1 = (const float*)d_in[11];
    const float* pg  = (const float*)d_in[12];
    const float* pbt = (const float*)d_in[13];
    const float* pm  = (const float*)d_in[14];
    const float* pv  = (const float*)d_in[15];
    const float* pw2 = (const float*)d_in[16];
    const float* pb2 = (const float*)d_in[17];
    const float* aw1 = (const float*)d_in[18];
    const float* ab1 = (const float*)d_in[19];
    const float* ag  = (const float*)d_in[20];
    const float* abt2= (const float*)d_in[21];
    const float* am  = (const float*)d_in[22];
    const float* av  = (const float*)d_in[23];
    const float* awt = (const float*)d_in[24];
    /* abt (d_in[25]) is constant along the softmax axis -> dropped */
    const float* we  = (const float*)d_in[26];
    const float* be  = (const float*)d_in[27];
    float* out = (float*)d_out;

    static int smem_set = 0;
    if (!smem_set) {
        cudaFuncSetAttribute(attn_kernel,
            cudaFuncAttributeMaxDynamicSharedMemorySize, SM_FLOATS*4);
        smem_set = 1;
    }

    setup_kernel<<<64, 256>>>(aw1, awt, we, ag, av, ab1, am, abt2);
    qkv_kernel<<<dim3(256, NB, 3), 256>>>(query, key_feat, wq, bq, wk, bk, wv, bv);
    knn_kernel<<<dim3(32, NB), 128>>>(pos1, pos2);
    prep_kernel<<<PTOT/2, 128>>>(pos1, pos2, pw1, pb1, pg, pbt, pm, pv, pw2, pb2);
    attn_kernel<<<MTOT/MT, 320, SM_FLOATS*4>>>();
    final_kernel<<<PTOT*2/16, 256>>>(query, be, out);
}

// round 4
// speedup vs baseline: 1.2615x; 1.2615x over previous
#include <cuda_runtime.h>
#include <math.h>

#define NB   4
#define NPT  4096
#define NS   4096
#define CIND 128
#define DIMD 64
#define KNNK 20
#define MTOT (NB*NPT*KNNK)   /* 327680 */
#define PTOT (NB*NPT)        /* 16384  */

// ---------------- static device scratch (no runtime allocation) ----------------
__device__ float g_q[PTOT*DIMD];
__device__ float g_k[PTOT*DIMD];
__device__ float g_v[PTOT*DIMD];
__device__ int   g_idx[PTOT*KNNK];
__device__ float g_h [MTOT*DIMD];     // [m][d]
__device__ float g_vg[MTOT*DIMD];     // [m][d]
__device__ float g_a [MTOT*256];      // [m][c]
__device__ float g_logits[MTOT*128];  // [m][r*64+o]
__device__ float g_agg[PTOT*2*DIMD];  // [q][d], q = point*2+r
__device__ float g_aw1t[64*256];      // [d][c]   transposed aw1
__device__ float g_w2t[256*128];      // [c][r*64+o]  permuted awt
__device__ float g_wet[64*128];       // [d][o2]  transposed we
__device__ float g_abn[512];          // [0:256) inv, [256:512) fused bias

// ---------------- packed f32x2 helpers ----------------
__device__ __forceinline__ unsigned long long ffma2(unsigned long long a,
                                                    unsigned long long b,
                                                    unsigned long long c) {
    unsigned long long d;
    asm("fma.rn.f32x2 %0, %1, %2, %3;" : "=l"(d) : "l"(a), "l"(b), "l"(c));
    return d;
}
__device__ __forceinline__ unsigned long long pack2(float lo, float hi) {
    unsigned long long d;
    asm("mov.b64 %0, {%1, %2};" : "=l"(d) : "f"(lo), "f"(hi));
    return d;
}
__device__ __forceinline__ float2 unpack2(unsigned long long v) {
    float2 r;
    asm("mov.b64 {%0, %1}, %2;" : "=f"(r.x), "=f"(r.y) : "l"(v));
    return r;
}

// ============================================================================
// Setup: transpose/permute weights, fold BN constants. One-shot, tiny.
// ============================================================================
__global__ void setup_kernel(const float* __restrict__ aw1, const float* __restrict__ awt,
                             const float* __restrict__ we,  const float* __restrict__ ag,
                             const float* __restrict__ av,  const float* __restrict__ ab1,
                             const float* __restrict__ am,  const float* __restrict__ abt2)
{
    int i0 = blockIdx.x*256 + threadIdx.x;
    int stride = gridDim.x*256;
    for (int i=i0; i<64*256; i+=stride) { int d=i>>8, c=i&255; g_aw1t[i] = aw1[c*64+d]; }
    for (int i=i0; i<256*128; i+=stride) {
        int c=i>>7, oo=i&127; int r=oo>>6, o=oo&63;
        g_w2t[i] = awt[c*128 + o*2 + r];
    }
    for (int i=i0; i<64*128; i+=stride) { int d=i>>7, o2=i&127; g_wet[i] = we[o2*64+d]; }
    for (int i=i0; i<256; i+=stride) {
        float inv = ag[i]*rsqrtf(av[i]+1e-5f);
        g_abn[i]     = inv;
        g_abn[256+i] = (ab1[i]-am[i])*inv + abt2[i];
    }
}

// ============================================================================
// Kernel 1: q/k/v 1x1 conv.
// ============================================================================
__global__ __launch_bounds__(256) void qkv_kernel(
    const float* __restrict__ query, const float* __restrict__ key_feat,
    const float* __restrict__ wq, const float* __restrict__ bq,
    const float* __restrict__ wk, const float* __restrict__ bk,
    const float* __restrict__ wv, const float* __restrict__ bv)
{
    __shared__ float Wsm[64*129];
    __shared__ __align__(16) float xs[128*16];
    int t = threadIdx.x;
    int z = blockIdx.z;
    const float* W    = (z==0)? wq : (z==1)? wk : wv;
    const float* bias = (z==0)? bq : (z==1)? bk : bv;
    const float* inp  = (z==0)? query : key_feat;
    float* outp       = (z==0)? g_q : (z==1)? g_k : g_v;
    int b  = blockIdx.y;
    int n0 = blockIdx.x * 16;

    for (int idx=t; idx<64*128; idx+=256) Wsm[(idx>>7)*129 + (idx&127)] = W[idx];
    for (int idx=t; idx<128*16; idx+=256) {
        int c = idx>>4, i = idx&15;
        xs[c*16+i] = inp[(b*CIND+c)*NPT + n0 + i];
    }
    __syncthreads();

    int d = t & 63, g = t >> 6;
    float bb = bias[d];
    float acc0=bb, acc1=bb, acc2=bb, acc3=bb;
    for (int c=0; c<128; ++c) {
        float w = Wsm[d*129+c];
        float4 v4 = *(const float4*)&xs[c*16 + g*4];
        acc0 += w*v4.x; acc1 += w*v4.y; acc2 += w*v4.z; acc3 += w*v4.w;
    }
    int pb = (b*NPT + n0 + g*4);
    outp[(pb+0)*DIMD + d] = acc0;
    outp[(pb+1)*DIMD + d] = acc1;
    outp[(pb+2)*DIMD + d] = acc2;
    outp[(pb+3)*DIMD + d] = acc3;
}

// ============================================================================
// Kernel 2: KNN (top-20 smallest d = |p1|^2+|p2|^2-2 p1.p2, stable ties).
// ============================================================================
__global__ __launch_bounds__(128) void knn_kernel(
    const float* __restrict__ pos1, const float* __restrict__ pos2)
{
    __shared__ float4 sp[2048];
    int t = threadIdx.x;
    int b = blockIdx.y;
    int n = blockIdx.x*128 + t;
    const float* p1 = pos1 + b*3*NPT;
    float qx = p1[n], qy = p1[NPT+n], qz = p1[2*NPT+n];
    float s1 = qx*qx + qy*qy + qz*qz;

    float bd[KNNK]; int bi[KNNK];
    #pragma unroll
    for (int i=0;i<KNNK;++i) { bd[i]=1e30f; bi[i]=0; }

    const float* p2 = pos2 + b*3*NS;
    for (int ch=0; ch<2; ++ch) {
        __syncthreads();
        for (int j=t; j<2048; j+=128) {
            int jg = ch*2048 + j;
            float x=p2[jg], y=p2[NS+jg], z=p2[2*NS+jg];
            sp[j] = make_float4(x, y, z, x*x+y*y+z*z);
        }
        __syncthreads();
        for (int j=0; j<2048; ++j) {
            float4 p = sp[j];
            float dd = s1 + p.w - 2.0f*(qx*p.x + qy*p.y + qz*p.z);
            if (dd < bd[KNNK-1]) {
                int jg = ch*2048 + j;
                #pragma unroll
                for (int i=KNNK-1; i>=1; --i) {
                    if (dd < bd[i]) {
                        bool sh = dd < bd[i-1];
                        bd[i] = sh ? bd[i-1] : dd;
                        bi[i] = sh ? bi[i-1] : jg;
                    }
                }
                if (dd < bd[0]) { bd[0]=dd; bi[0]=jg; }
            }
        }
    }
    int* op = &g_idx[(b*NPT + n)*KNNK];
    #pragma unroll
    for (int i=0;i<KNNK;++i) op[i] = bi[i];
}

// ============================================================================
// Kernel 3: gather + pos-MLP; h = q - k_g + pe ; vg = v_g + pe
// ============================================================================
__global__ __launch_bounds__(128) void prep_kernel(
    const float* __restrict__ pos1, const float* __restrict__ pos2,
    const float* __restrict__ pw1, const float* __restrict__ pb1,
    const float* __restrict__ pg,  const float* __restrict__ pbt,
    const float* __restrict__ pm,  const float* __restrict__ pvv,
    const float* __restrict__ pw2, const float* __restrict__ pb2)
{
    __shared__ float pw2s[64*65];
    __shared__ __align__(16) float pe1s[2][64*24];
    __shared__ float prel[2][3][KNNK];
    __shared__ float qs[2][64];
    __shared__ int idxs[2][KNNK];
    int t = threadIdx.x;
    int p0 = blockIdx.x*2;

    for (int idx=t; idx<64*64; idx+=128) pw2s[(idx>>6)*65 + (idx&63)] = pw2[idx];
    if (t < 2*KNNK) idxs[t/KNNK][t%KNNK] = g_idx[p0*KNNK + t];
    {
        int pp = t>>6, d = t&63;
        qs[pp][d] = g_q[(p0+pp)*DIMD + d];
    }
    __syncthreads();

    if (t < 2*3*KNNK) {
        int pp = t/(3*KNNK), r = t%(3*KNNK);
        int c = r/KNNK, k = r%KNNK;
        int p = p0+pp, b = p>>12, n = p&4095;
        prel[pp][c][k] = pos1[(b*3+c)*NPT + n] - pos2[(b*3+c)*NS + idxs[pp][k]];
    }
    __syncthreads();

    {   // pe1 = relu(bn(pw1 @ pos_rel + pb1))
        int cH = t & 63, pp = t >> 6;
        float w0 = pw1[cH*3], w1 = pw1[cH*3+1], w2v = pw1[cH*3+2];
        float inv = pg[cH]*rsqrtf(pvv[cH]+1e-5f);
        float tb  = (pb1[cH]-pm[cH])*inv + pbt[cH];
        #pragma unroll
        for (int k=0;k<KNNK;++k) {
            float s = w0*prel[pp][0][k] + w1*prel[pp][1][k] + w2v*prel[pp][2][k];
            pe1s[pp][cH*24+k] = fmaxf(s*inv + tb, 0.0f);
        }
    }
    __syncthreads();

    {   // pe = pw2 @ pe1 + pb2 ; emit h, vg
        int d = t&63, pp = t>>6;
        int p = p0+pp, b = p>>12;
        float acc[KNNK]; float bias = pb2[d];
        #pragma unroll
        for (int k=0;k<KNNK;++k) acc[k]=bias;
        for (int cH=0;cH<64;++cH) {
            float w = pw2s[d*65+cH];
            #pragma unroll
            for (int k4=0;k4<5;++k4) {
                float4 v4 = *(const float4*)&pe1s[pp][cH*24 + k4*4];
                acc[k4*4+0]+=w*v4.x; acc[k4*4+1]+=w*v4.y;
                acc[k4*4+2]+=w*v4.z; acc[k4*4+3]+=w*v4.w;
            }
        }
        float qv = qs[pp][d];
        #pragma unroll
        for (int k=0;k<KNNK;++k) {
            int j = idxs[pp][k];
            int m = p*KNNK + k;
            float kg = g_k[(b*NS+j)*DIMD + d];
            float vv = g_v[(b*NS+j)*DIMD + d];
            g_h [m*DIMD + d] = qv - kg + acc[k];
            g_vg[m*DIMD + d] = vv + acc[k];
        }
    }
}

// ============================================================================
// Kernel 4: GEMM1  a[m][c] = relu(bn_fused(aw1t . h)), c in 256, K=64.
// grid 5120 (64 m/CTA), block 256 (8 warps x 8 m-rows). FFMA2 packed along m.
// smem: hst [d=64][m=64 pad66] = 16.9KB -> 2+ CTAs/SM.
// Per d-iter/thread: 4 LDS.64 (bcast) + 2 LDG.128 + 8 pack + 32 FFMA2.
// ============================================================================
__global__ __launch_bounds__(256) void gemm1_kernel()
{
    __shared__ float hst[64*66];
    int t = threadIdx.x;
    int w = t >> 5, cg = t & 31;
    int m0 = blockIdx.x*64;

    for (int idx=t; idx<64*64; idx+=256) {
        int m = idx>>6, d = idx&63;
        hst[d*66 + m] = g_h[(m0+m)*64 + d];
    }
    __syncthreads();

    unsigned long long acc[8][4];
    #pragma unroll
    for (int j=0;j<8;++j)
        #pragma unroll
        for (int q=0;q<4;++q) acc[j][q] = 0ull;

    const int mb = w*8;
    for (int d=0; d<64; ++d) {
        unsigned long long hv[4];
        #pragma unroll
        for (int q=0;q<4;++q)
            hv[q] = *(const unsigned long long*)&hst[d*66 + mb + 2*q];
        float4 w0 = __ldg((const float4*)&g_aw1t[d*256 + cg*8]);
        float4 w1 = __ldg((const float4*)&g_aw1t[d*256 + cg*8 + 4]);
        float wv[8] = {w0.x,w0.y,w0.z,w0.w,w1.x,w1.y,w1.z,w1.w};
        #pragma unroll
        for (int j=0;j<8;++j) {
            unsigned long long wp = pack2(wv[j], wv[j]);
            #pragma unroll
            for (int q=0;q<4;++q) acc[j][q] = ffma2(wp, hv[q], acc[j][q]);
        }
    }

    // epilogue: BN+ReLU, reassemble per-m rows of 8 consecutive c -> 2x STG.128
    float4 iv0 = __ldg((const float4*)&g_abn[cg*8]);
    float4 iv1 = __ldg((const float4*)&g_abn[cg*8+4]);
    float4 tb0 = __ldg((const float4*)&g_abn[256+cg*8]);
    float4 tb1 = __ldg((const float4*)&g_abn[256+cg*8+4]);
    float inv[8] = {iv0.x,iv0.y,iv0.z,iv0.w,iv1.x,iv1.y,iv1.z,iv1.w};
    float tb [8] = {tb0.x,tb0.y,tb0.z,tb0.w,tb1.x,tb1.y,tb1.z,tb1.w};

    #pragma unroll
    for (int q=0;q<4;++q) {
        float2 vv[8];
        #pragma unroll
        for (int j=0;j<8;++j) vv[j] = unpack2(acc[j][q]);
        #pragma unroll
        for (int half=0; half<2; ++half) {
            int m = m0 + mb + 2*q + half;
            float o[8];
            #pragma unroll
            for (int j=0;j<8;++j) {
                float x = half ? vv[j].y : vv[j].x;
                o[j] = fmaxf(fmaf(x, inv[j], tb[j]), 0.f);
            }
            float* dst = &g_a[m*256 + cg*8];
            *(float4*)dst       = make_float4(o[0],o[1],o[2],o[3]);
            *(float4*)(dst + 4) = make_float4(o[4],o[5],o[6],o[7]);
        }
    }
}

// ============================================================================
// Kernel 5: GEMM2  logits[m][o'] = w2t . a, o' in 128, K=256 (2 chunks).
// grid 5120, block 256. FFMA2 packed along m, 4 consecutive o' per thread.
// smem: ast [c=128][m=64 pad66] = 33.8KB -> 2 CTAs/SM.
// Per cc-iter/thread: 4 LDS.64 (bcast) + 1 LDG.128 + 4 pack + 16 FFMA2.
// ============================================================================
__global__ __launch_bounds__(256) void gemm2_kernel()
{
    __shared__ float ast[128*66];
    int t = threadIdx.x;
    int w = t >> 5, cg = t & 31;
    int m0 = blockIdx.x*64;
    const int mb = w*8;

    unsigned long long acc[4][4];
    #pragma unroll
    for (int j=0;j<4;++j)
        #pragma unroll
        for (int q=0;q<4;++q) acc[j][q] = 0ull;

    for (int ch=0; ch<2; ++ch) {
        __syncthreads();
        for (int idx=t; idx<64*128; idx+=256) {
            int m = idx>>7, c = idx&127;
            ast[c*66 + m] = g_a[(m0+m)*256 + ch*128 + c];
        }
        __syncthreads();
        for (int cc=0; cc<128; ++cc) {
            unsigned long long hv[4];
            #pragma unroll
            for (int q=0;q<4;++q)
                hv[q] = *(const unsigned long long*)&ast[cc*66 + mb + 2*q];
            float4 wv = __ldg((const float4*)&g_w2t[(ch*128+cc)*128 + cg*4]);
            float wa[4] = {wv.x, wv.y, wv.z, wv.w};
            #pragma unroll
            for (int j=0;j<4;++j) {
                unsigned long long wp = pack2(wa[j], wa[j]);
                #pragma unroll
                for (int q=0;q<4;++q) acc[j][q] = ffma2(wp, hv[q], acc[j][q]);
            }
        }
    }

    #pragma unroll
    for (int q=0;q<4;++q) {
        float2 vv[4];
        #pragma unroll
        for (int j=0;j<4;++j) vv[j] = unpack2(acc[j][q]);
        #pragma unroll
        for (int half=0; half<2; ++half) {
            int m = m0 + mb + 2*q + half;
            float* dst = &g_logits[m*128 + cg*4];
            *(float4*)dst = half ? make_float4(vv[0].y,vv[1].y,vv[2].y,vv[3].y)
                                 : make_float4(vv[0].x,vv[1].x,vv[2].x,vv[3].x);
        }
    }
}

// ============================================================================
// Kernel 6: softmax over k (=20) + weighted aggregation of vg.
// ============================================================================
__global__ __launch_bounds__(256) void softmax_kernel()
{
    int t = threadIdx.x;
    int p = blockIdx.x*2 + (t>>7);
    int chn = t & 127;          // r*64 + d
    int d = chn & 63;

    const float* lp = &g_logits[p*KNNK*128 + chn];
    float lg[KNNK];
    #pragma unroll
    for (int k=0;k<KNNK;++k) lg[k] = lp[k*128];
    float mx = lg[0];
    #pragma unroll
    for (int k=1;k<KNNK;++k) mx = fmaxf(mx, lg[k]);
    float s = 0.f;
    #pragma unroll
    for (int k=0;k<KNNK;++k) { lg[k] = __expf(lg[k]-mx); s += lg[k]; }
    float inv = 1.f/s;

    const float* vp = &g_vg[p*KNNK*64 + d];
    float acc = 0.f;
    #pragma unroll
    for (int k=0;k<KNNK;++k) acc += lg[k]*vp[k*64];
    g_agg[p*128 + chn] = acc*inv;
}

// ============================================================================
// Kernel 7: final 1x1 conv (DIM->CIN) + residual (nearest-upsampled query).
// ============================================================================
__global__ __launch_bounds__(256) void final_kernel(
    const float* __restrict__ query, const float* __restrict__ be,
    float* __restrict__ out)
{
    __shared__ float wes[64*128];
    __shared__ __align__(16) float aggt[64*16];
    int t = threadIdx.x;
    int q0 = blockIdx.x*16;
    for (int idx=t; idx<64*128; idx+=256) wes[idx] = g_wet[idx];
    for (int idx=t; idx<16*64; idx+=256) {
        int li = idx>>6, d = idx&63;
        aggt[d*16+li] = g_agg[(q0+li)*64 + d];
    }
    __syncthreads();

    int o2 = t & 127, h = t >> 7;
    float acc[8];
    #pragma unroll
    for (int i=0;i<8;++i) acc[i]=0.f;
    for (int d=0; d<64; ++d) {
        float w = wes[d*128+o2];
        float4 a0 = *(const float4*)&aggt[d*16 + h*8];
        float4 a1 = *(const float4*)&aggt[d*16 + h*8 + 4];
        acc[0]+=w*a0.x; acc[1]+=w*a0.y; acc[2]+=w*a0.z; acc[3]+=w*a0.w;
        acc[4]+=w*a1.x; acc[5]+=w*a1.y; acc[6]+=w*a1.z; acc[7]+=w*a1.w;
    }
    float bb = be[o2];
    #pragma unroll
    for (int i=0;i<8;++i) {
        int qq = q0 + h*8 + i;
        int b = qq >> 13, nr = qq & 8191, n = nr >> 1;
        out[b*(128*8192) + o2*8192 + nr] = acc[i] + bb
            + query[b*(128*4096) + o2*4096 + n];
    }
}

// ============================================================================
extern "C" void kernel_launch(void* const* d_in, const int* in_sizes, int n_in,
                              void* d_out, int out_size)
{
    const float* pos1     = (const float*)d_in[0];
    const float* query    = (const float*)d_in[1];
    const float* pos2     = (const float*)d_in[2];
    const float* key_feat = (const float*)d_in[3];
    const float* wq  = (const float*)d_in[4];
    const float* bq  = (const float*)d_in[5];
    const float* wk  = (const float*)d_in[6];
    const float* bk  = (const float*)d_in[7];
    const float* wv  = (const float*)d_in[8];
    const float* bv  = (const float*)d_in[9];
    const float* pw1 = (const float*)d_in[10];
    const float* pb1 = (const float*)d_in[11];
    const float* pg  = (const float*)d_in[12];
    const float* pbt = (const float*)d_in[13];
    const float* pm  = (const float*)d_in[14];
    const float* pv  = (const float*)d_in[15];
    const float* pw2 = (const float*)d_in[16];
    const float* pb2 = (const float*)d_in[17];
    const float* aw1 = (const float*)d_in[18];
    const float* ab1 = (const float*)d_in[19];
    const float* ag  = (const float*)d_in[20];
    const float* abt2= (const float*)d_in[21];
    const float* am  = (const float*)d_in[22];
    const float* av  = (const float*)d_in[23];
    const float* awt = (const float*)d_in[24];
    /* abt (d_in[25]) is constant along the softmax axis -> dropped */
    const float* we  = (const float*)d_in[26];
    const float* be  = (const float*)d_in[27];
    float* out = (float*)d_out;

    setup_kernel<<<64, 256>>>(aw1, awt, we, ag, av, ab1, am, abt2);
    qkv_kernel<<<dim3(256, NB, 3), 256>>>(query, key_feat, wq, bq, wk, bk, wv, bv);
    knn_kernel<<<dim3(32, NB), 128>>>(pos1, pos2);
    prep_kernel<<<PTOT/2, 128>>>(pos1, pos2, pw1, pb1, pg, pbt, pm, pv, pw2, pb2);
    gemm1_kernel<<<MTOT/64, 256>>>();
    gemm2_kernel<<<MTOT/64, 256>>>();
    softmax_kernel<<<PTOT/2, 256>>>();
    final_kernel<<<PTOT*2/16, 256>>>(query, be, out);
}

// round 5
// speedup vs baseline: 1.7023x; 1.3495x over previous
#include <cuda_runtime.h>
#include <math.h>

#define NB   4
#define NPT  4096
#define NS   4096
#define CIND 128
#define DIMD 64
#define KNNK 20
#define MTOT (NB*NPT*KNNK)   /* 327680 */
#define PTOT (NB*NPT)        /* 16384  */

// ---------------- static device scratch (no runtime allocation) ----------------
__device__ float g_q[PTOT*DIMD];
__device__ float g_k[PTOT*DIMD];
__device__ float g_v[PTOT*DIMD];
__device__ int   g_idx[PTOT*KNNK];
__device__ float g_h [MTOT*DIMD];     // [m][d]
__device__ float g_vg[MTOT*DIMD];     // [m][d]
__device__ float g_logits[MTOT*128];  // [m][r*64+o]
__device__ float g_agg[PTOT*2*DIMD];  // [q][d], q = point*2+r
__device__ float g_wet[64*128];       // [d][o2]  transposed we
__device__ float g_abn[512];          // [0:256) inv, [256:512) fused bias
// fragment-ordered, hi/lo-split weights for tensor-core GEMMs
__device__ float g_w1f[8*32*32*4];    // [s][nfg][lane][b0hi,b0lo,b1hi,b1lo]
__device__ float g_w2f[32*16*32*4];   // [s][nfg][lane][b0hi,b0lo,b1hi,b1lo]

// ---------------- helpers ----------------
__device__ __forceinline__ float tf32_hi(float x) {
    return __int_as_float(__float_as_int(x) & 0xFFFFE000);
}
__device__ __forceinline__ void mma_tf32(float* d, const unsigned* a, const unsigned* b) {
    asm volatile(
        "mma.sync.aligned.m16n8k8.row.col.f32.tf32.tf32.f32 "
        "{%0,%1,%2,%3}, {%4,%5,%6,%7}, {%8,%9}, {%0,%1,%2,%3};"
        : "+f"(d[0]), "+f"(d[1]), "+f"(d[2]), "+f"(d[3])
        : "r"(a[0]), "r"(a[1]), "r"(a[2]), "r"(a[3]), "r"(b[0]), "r"(b[1]));
}

// ============================================================================
// Setup: fragment-order + hi/lo split the GEMM weights, fold BN, transpose we.
// ============================================================================
__global__ void setup_kernel(const float* __restrict__ aw1, const float* __restrict__ awt,
                             const float* __restrict__ we,  const float* __restrict__ ag,
                             const float* __restrict__ av,  const float* __restrict__ ab1,
                             const float* __restrict__ am,  const float* __restrict__ abt2)
{
    int i0 = blockIdx.x*256 + threadIdx.x;
    int stride = gridDim.x*256;

    // g_w1f: GEMM1 B-frags. B[k][n] = aw1[n*64+k], k<64, n<256.
    for (int i=i0; i<8*32*32; i+=stride) {
        int lane = i & 31, nfg = (i>>5)&31, s = i>>10;
        int gr = lane>>2, tig = lane&3;
        int n = nfg*8 + gr;
        int k0 = s*8 + tig, k1 = k0 + 4;
        float b0 = aw1[n*64 + k0], b1 = aw1[n*64 + k1];
        float b0h = tf32_hi(b0), b1h = tf32_hi(b1);
        float4 o = make_float4(b0h, b0-b0h, b1h, b1-b1h);
        *(float4*)&g_w1f[i*4] = o;
    }
    // g_w2f: GEMM2 B-frags. B[k][n=o'] = awt[k*128 + (o'&63)*2 + (o'>>6)], k<256, n<128.
    for (int i=i0; i<32*16*32; i+=stride) {
        int lane = i & 31, nfg = (i>>5)&15, s = i>>9;
        int gr = lane>>2, tig = lane&3;
        int n = nfg*8 + gr;
        int k0 = s*8 + tig, k1 = k0 + 4;
        float b0 = awt[k0*128 + (n&63)*2 + (n>>6)];
        float b1 = awt[k1*128 + (n&63)*2 + (n>>6)];
        float b0h = tf32_hi(b0), b1h = tf32_hi(b1);
        float4 o = make_float4(b0h, b0-b0h, b1h, b1-b1h);
        *(float4*)&g_w2f[i*4] = o;
    }
    for (int i=i0; i<64*128; i+=stride) { int d=i>>7, o2=i&127; g_wet[i] = we[o2*64+d]; }
    for (int i=i0; i<256; i+=stride) {
        float inv = ag[i]*rsqrtf(av[i]+1e-5f);
        g_abn[i]     = inv;
        g_abn[256+i] = (ab1[i]-am[i])*inv + abt2[i];
    }
}

// ============================================================================
// Kernel 1: q/k/v 1x1 conv.
// ============================================================================
__global__ __launch_bounds__(256) void qkv_kernel(
    const float* __restrict__ query, const float* __restrict__ key_feat,
    const float* __restrict__ wq, const float* __restrict__ bq,
    const float* __restrict__ wk, const float* __restrict__ bk,
    const float* __restrict__ wv, const float* __restrict__ bv)
{
    __shared__ float Wsm[64*129];
    __shared__ __align__(16) float xs[128*16];
    int t = threadIdx.x;
    int z = blockIdx.z;
    const float* W    = (z==0)? wq : (z==1)? wk : wv;
    const float* bias = (z==0)? bq : (z==1)? bk : bv;
    const float* inp  = (z==0)? query : key_feat;
    float* outp       = (z==0)? g_q : (z==1)? g_k : g_v;
    int b  = blockIdx.y;
    int n0 = blockIdx.x * 16;

    for (int idx=t; idx<64*128; idx+=256) Wsm[(idx>>7)*129 + (idx&127)] = W[idx];
    for (int idx=t; idx<128*16; idx+=256) {
        int c = idx>>4, i = idx&15;
        xs[c*16+i] = inp[(b*CIND+c)*NPT + n0 + i];
    }
    __syncthreads();

    int d = t & 63, g = t >> 6;
    float bb = bias[d];
    float acc0=bb, acc1=bb, acc2=bb, acc3=bb;
    for (int c=0; c<128; ++c) {
        float w = Wsm[d*129+c];
        float4 v4 = *(const float4*)&xs[c*16 + g*4];
        acc0 += w*v4.x; acc1 += w*v4.y; acc2 += w*v4.z; acc3 += w*v4.w;
    }
    int pb = (b*NPT + n0 + g*4);
    outp[(pb+0)*DIMD + d] = acc0;
    outp[(pb+1)*DIMD + d] = acc1;
    outp[(pb+2)*DIMD + d] = acc2;
    outp[(pb+3)*DIMD + d] = acc3;
}

// ============================================================================
// Kernel 2: KNN (top-20 smallest d = |p1|^2+|p2|^2-2 p1.p2, stable ties).
// ============================================================================
__global__ __launch_bounds__(128) void knn_kernel(
    const float* __restrict__ pos1, const float* __restrict__ pos2)
{
    __shared__ float4 sp[2048];
    int t = threadIdx.x;
    int b = blockIdx.y;
    int n = blockIdx.x*128 + t;
    const float* p1 = pos1 + b*3*NPT;
    float qx = p1[n], qy = p1[NPT+n], qz = p1[2*NPT+n];
    float s1 = qx*qx + qy*qy + qz*qz;

    float bd[KNNK]; int bi[KNNK];
    #pragma unroll
    for (int i=0;i<KNNK;++i) { bd[i]=1e30f; bi[i]=0; }

    const float* p2 = pos2 + b*3*NS;
    for (int ch=0; ch<2; ++ch) {
        __syncthreads();
        for (int j=t; j<2048; j+=128) {
            int jg = ch*2048 + j;
            float x=p2[jg], y=p2[NS+jg], z=p2[2*NS+jg];
            sp[j] = make_float4(x, y, z, x*x+y*y+z*z);
        }
        __syncthreads();
        for (int j=0; j<2048; ++j) {
            float4 p = sp[j];
            float dd = s1 + p.w - 2.0f*(qx*p.x + qy*p.y + qz*p.z);
            if (dd < bd[KNNK-1]) {
                int jg = ch*2048 + j;
                #pragma unroll
                for (int i=KNNK-1; i>=1; --i) {
                    if (dd < bd[i]) {
                        bool sh = dd < bd[i-1];
                        bd[i] = sh ? bd[i-1] : dd;
                        bi[i] = sh ? bi[i-1] : jg;
                    }
                }
                if (dd < bd[0]) { bd[0]=dd; bi[0]=jg; }
            }
        }
    }
    int* op = &g_idx[(b*NPT + n)*KNNK];
    #pragma unroll
    for (int i=0;i<KNNK;++i) op[i] = bi[i];
}

// ============================================================================
// Kernel 3: gather + pos-MLP; h = q - k_g + pe ; vg = v_g + pe
// ============================================================================
__global__ __launch_bounds__(128) void prep_kernel(
    const float* __restrict__ pos1, const float* __restrict__ pos2,
    const float* __restrict__ pw1, const float* __restrict__ pb1,
    const float* __restrict__ pg,  const float* __restrict__ pbt,
    const float* __restrict__ pm,  const float* __restrict__ pvv,
    const float* __restrict__ pw2, const float* __restrict__ pb2)
{
    __shared__ float pw2s[64*65];
    __shared__ __align__(16) float pe1s[2][64*24];
    __shared__ float prel[2][3][KNNK];
    __shared__ float qs[2][64];
    __shared__ int idxs[2][KNNK];
    int t = threadIdx.x;
    int p0 = blockIdx.x*2;

    for (int idx=t; idx<64*64; idx+=128) pw2s[(idx>>6)*65 + (idx&63)] = pw2[idx];
    if (t < 2*KNNK) idxs[t/KNNK][t%KNNK] = g_idx[p0*KNNK + t];
    {
        int pp = t>>6, d = t&63;
        qs[pp][d] = g_q[(p0+pp)*DIMD + d];
    }
    __syncthreads();

    if (t < 2*3*KNNK) {
        int pp = t/(3*KNNK), r = t%(3*KNNK);
        int c = r/KNNK, k = r%KNNK;
        int p = p0+pp, b = p>>12, n = p&4095;
        prel[pp][c][k] = pos1[(b*3+c)*NPT + n] - pos2[(b*3+c)*NS + idxs[pp][k]];
    }
    __syncthreads();

    {   // pe1 = relu(bn(pw1 @ pos_rel + pb1))
        int cH = t & 63, pp = t >> 6;
        float w0 = pw1[cH*3], w1 = pw1[cH*3+1], w2v = pw1[cH*3+2];
        float inv = pg[cH]*rsqrtf(pvv[cH]+1e-5f);
        float tb  = (pb1[cH]-pm[cH])*inv + pbt[cH];
        #pragma unroll
        for (int k=0;k<KNNK;++k) {
            float s = w0*prel[pp][0][k] + w1*prel[pp][1][k] + w2v*prel[pp][2][k];
            pe1s[pp][cH*24+k] = fmaxf(s*inv + tb, 0.0f);
        }
    }
    __syncthreads();

    {   // pe = pw2 @ pe1 + pb2 ; emit h, vg
        int d = t&63, pp = t>>6;
        int p = p0+pp, b = p>>12;
        float acc[KNNK]; float bias = pb2[d];
        #pragma unroll
        for (int k=0;k<KNNK;++k) acc[k]=bias;
        for (int cH=0;cH<64;++cH) {
            float w = pw2s[d*65+cH];
            #pragma unroll
            for (int k4=0;k4<5;++k4) {
                float4 v4 = *(const float4*)&pe1s[pp][cH*24 + k4*4];
                acc[k4*4+0]+=w*v4.x; acc[k4*4+1]+=w*v4.y;
                acc[k4*4+2]+=w*v4.z; acc[k4*4+3]+=w*v4.w;
            }
        }
        float qv = qs[pp][d];
        #pragma unroll
        for (int k=0;k<KNNK;++k) {
            int j = idxs[pp][k];
            int m = p*KNNK + k;
            float kg = g_k[(b*NS+j)*DIMD + d];
            float vv = g_v[(b*NS+j)*DIMD + d];
            g_h [m*DIMD + d] = qv - kg + acc[k];
            g_vg[m*DIMD + d] = vv + acc[k];
        }
    }
}

// ============================================================================
// Kernel 4 (FUSED, tensor-core): gemm1 + BN/ReLU + gemm2, 3xTF32 mma.sync.
// CTA = 64 m-rows. Block 256 = 8 warps: mw = w&1 (m half), cw = w>>2... (w>>1).
// Phase 1: a[64m][256c] = relu(bn(h @ W1^T)), K=64  -> smem ast.
// Phase 2: logits[64m][128o'] = a @ W2^T, K=256     -> g_logits.
// smem: hst [64m][64k] pad68 (17.4KB) + ast [64m][256k] pad260 (66.6KB) = 84KB.
// ============================================================================
#define HST_STRIDE 68
#define AST_STRIDE 260
#define SMEM_ATTN ((64*HST_STRIDE + 64*AST_STRIDE)*4)

__global__ __launch_bounds__(256, 2) void attn_gemm_kernel()
{
    extern __shared__ __align__(16) float sm[];
    float* hst = sm;                    // [m][k] stride 68
    float* ast = sm + 64*HST_STRIDE;    // [m][k] stride 260
    int t = threadIdx.x;
    int w = t >> 5, lane = t & 31;
    int gr = lane >> 2, tig = lane & 3;
    int mw = w & 1, cw = w >> 1;
    int m0 = blockIdx.x * 64;

    // load h tile (coalesced read, conflict-free write)
    for (int idx = t; idx < 64*64; idx += 256) {
        int m = idx >> 6, k = idx & 63;
        hst[m*HST_STRIDE + k] = g_h[(m0+m)*64 + k];
    }
    __syncthreads();

    // ---------------- phase 1: 64m x 256c, K=64 ----------------
    {
        float acc[2][8][4];
        #pragma unroll
        for (int mf=0;mf<2;++mf)
            #pragma unroll
            for (int nf=0;nf<8;++nf)
                #pragma unroll
                for (int q=0;q<4;++q) acc[mf][nf][q] = 0.f;

        #pragma unroll
        for (int s=0; s<8; ++s) {
            unsigned ahi[2][4], alo[2][4];
            #pragma unroll
            for (int mf=0;mf<2;++mf) {
                int r0 = mw*32 + mf*16 + gr;
                float e0 = hst[(r0  )*HST_STRIDE + s*8 + tig];
                float e1 = hst[(r0+8)*HST_STRIDE + s*8 + tig];
                float e2 = hst[(r0  )*HST_STRIDE + s*8 + tig + 4];
                float e3 = hst[(r0+8)*HST_STRIDE + s*8 + tig + 4];
                float h0=tf32_hi(e0), h1=tf32_hi(e1), h2=tf32_hi(e2), h3=tf32_hi(e3);
                ahi[mf][0]=__float_as_uint(h0); alo[mf][0]=__float_as_uint(e0-h0);
                ahi[mf][1]=__float_as_uint(h1); alo[mf][1]=__float_as_uint(e1-h1);
                ahi[mf][2]=__float_as_uint(h2); alo[mf][2]=__float_as_uint(e2-h2);
                ahi[mf][3]=__float_as_uint(h3); alo[mf][3]=__float_as_uint(e3-h3);
            }
            #pragma unroll
            for (int nf=0;nf<8;++nf) {
                float4 wf = __ldg((const float4*)&g_w1f[((s*32 + cw*8 + nf)*32 + lane)*4]);
                unsigned bhi[2] = {__float_as_uint(wf.x), __float_as_uint(wf.z)};
                unsigned blo[2] = {__float_as_uint(wf.y), __float_as_uint(wf.w)};
                #pragma unroll
                for (int mf=0;mf<2;++mf) {
                    mma_tf32(acc[mf][nf], ahi[mf], bhi);
                    mma_tf32(acc[mf][nf], ahi[mf], blo);
                    mma_tf32(acc[mf][nf], alo[mf], bhi);
                }
            }
        }

        // epilogue: BN + ReLU -> ast
        #pragma unroll
        for (int nf=0;nf<8;++nf) {
            int cb = cw*64 + nf*8 + 2*tig;
            float2 iv = __ldg((const float2*)&g_abn[cb]);
            float2 tb = __ldg((const float2*)&g_abn[256+cb]);
            #pragma unroll
            for (int mf=0;mf<2;++mf) {
                int r0 = mw*32 + mf*16 + gr;
                float v0 = fmaxf(fmaf(acc[mf][nf][0], iv.x, tb.x), 0.f);
                float v1 = fmaxf(fmaf(acc[mf][nf][1], iv.y, tb.y), 0.f);
                float v2 = fmaxf(fmaf(acc[mf][nf][2], iv.x, tb.x), 0.f);
                float v3 = fmaxf(fmaf(acc[mf][nf][3], iv.y, tb.y), 0.f);
                *(float2*)&ast[(r0  )*AST_STRIDE + cb] = make_float2(v0, v1);
                *(float2*)&ast[(r0+8)*AST_STRIDE + cb] = make_float2(v2, v3);
            }
        }
    }
    __syncthreads();

    // ---------------- phase 2: 64m x 128o', K=256 ----------------
    {
        float acc[2][4][4];
        #pragma unroll
        for (int mf=0;mf<2;++mf)
            #pragma unroll
            for (int nf=0;nf<4;++nf)
                #pragma unroll
                for (int q=0;q<4;++q) acc[mf][nf][q] = 0.f;

        for (int s=0; s<32; ++s) {
            unsigned ahi[2][4], alo[2][4];
            #pragma unroll
            for (int mf=0;mf<2;++mf) {
                int r0 = mw*32 + mf*16 + gr;
                float e0 = ast[(r0  )*AST_STRIDE + s*8 + tig];
                float e1 = ast[(r0+8)*AST_STRIDE + s*8 + tig];
                float e2 = ast[(r0  )*AST_STRIDE + s*8 + tig + 4];
                float e3 = ast[(r0+8)*AST_STRIDE + s*8 + tig + 4];
                float h0=tf32_hi(e0), h1=tf32_hi(e1), h2=tf32_hi(e2), h3=tf32_hi(e3);
                ahi[mf][0]=__float_as_uint(h0); alo[mf][0]=__float_as_uint(e0-h0);
                ahi[mf][1]=__float_as_uint(h1); alo[mf][1]=__float_as_uint(e1-h1);
                ahi[mf][2]=__float_as_uint(h2); alo[mf][2]=__float_as_uint(e2-h2);
                ahi[mf][3]=__float_as_uint(h3); alo[mf][3]=__float_as_uint(e3-h3);
            }
            #pragma unroll
            for (int nf=0;nf<4;++nf) {
                float4 wf = __ldg((const float4*)&g_w2f[((s*16 + cw*4 + nf)*32 + lane)*4]);
                unsigned bhi[2] = {__float_as_uint(wf.x), __float_as_uint(wf.z)};
                unsigned blo[2] = {__float_as_uint(wf.y), __float_as_uint(wf.w)};
                #pragma unroll
                for (int mf=0;mf<2;++mf) {
                    mma_tf32(acc[mf][nf], ahi[mf], bhi);
                    mma_tf32(acc[mf][nf], ahi[mf], blo);
                    mma_tf32(acc[mf][nf], alo[mf], bhi);
                }
            }
        }

        // epilogue: store logits (float2 per fragment row)
        #pragma unroll
        for (int nf=0;nf<4;++nf) {
            int ob = cw*32 + nf*8 + 2*tig;
            #pragma unroll
            for (int mf=0;mf<2;++mf) {
                int r0 = m0 + mw*32 + mf*16 + gr;
                *(float2*)&g_logits[(r0  )*128 + ob] = make_float2(acc[mf][nf][0], acc[mf][nf][1]);
                *(float2*)&g_logits[(r0+8)*128 + ob] = make_float2(acc[mf][nf][2], acc[mf][nf][3]);
            }
        }
    }
}

// ============================================================================
// Kernel 5: softmax over k (=20) + weighted aggregation of vg.
// ============================================================================
__global__ __launch_bounds__(256) void softmax_kernel()
{
    int t = threadIdx.x;
    int p = blockIdx.x*2 + (t>>7);
    int chn = t & 127;          // r*64 + d
    int d = chn & 63;

    const float* lp = &g_logits[p*KNNK*128 + chn];
    float lg[KNNK];
    #pragma unroll
    for (int k=0;k<KNNK;++k) lg[k] = lp[k*128];
    float mx = lg[0];
    #pragma unroll
    for (int k=1;k<KNNK;++k) mx = fmaxf(mx, lg[k]);
    float s = 0.f;
    #pragma unroll
    for (int k=0;k<KNNK;++k) { lg[k] = __expf(lg[k]-mx); s += lg[k]; }
    float inv = 1.f/s;

    const float* vp = &g_vg[p*KNNK*64 + d];
    float acc = 0.f;
    #pragma unroll
    for (int k=0;k<KNNK;++k) acc += lg[k]*vp[k*64];
    g_agg[p*128 + chn] = acc*inv;
}

// ============================================================================
// Kernel 6: final 1x1 conv (DIM->CIN) + residual (nearest-upsampled query).
// ============================================================================
__global__ __launch_bounds__(256) void final_kernel(
    const float* __restrict__ query, const float* __restrict__ be,
    float* __restrict__ out)
{
    __shared__ float wes[64*128];
    __shared__ __align__(16) float aggt[64*16];
    int t = threadIdx.x;
    int q0 = blockIdx.x*16;
    for (int idx=t; idx<64*128; idx+=256) wes[idx] = g_wet[idx];
    for (int idx=t; idx<16*64; idx+=256) {
        int li = idx>>6, d = idx&63;
        aggt[d*16+li] = g_agg[(q0+li)*64 + d];
    }
    __syncthreads();

    int o2 = t & 127, h = t >> 7;
    float acc[8];
    #pragma unroll
    for (int i=0;i<8;++i) acc[i]=0.f;
    for (int d=0; d<64; ++d) {
        float w = wes[d*128+o2];
        float4 a0 = *(const float4*)&aggt[d*16 + h*8];
        float4 a1 = *(const float4*)&aggt[d*16 + h*8 + 4];
        acc[0]+=w*a0.x; acc[1]+=w*a0.y; acc[2]+=w*a0.z; acc[3]+=w*a0.w;
        acc[4]+=w*a1.x; acc[5]+=w*a1.y; acc[6]+=w*a1.z; acc[7]+=w*a1.w;
    }
    float bb = be[o2];
    #pragma unroll
    for (int i=0;i<8;++i) {
        int qq = q0 + h*8 + i;
        int b = qq >> 13, nr = qq & 8191, n = nr >> 1;
        out[b*(128*8192) + o2*8192 + nr] = acc[i] + bb
            + query[b*(128*4096) + o2*4096 + n];
    }
}

// ============================================================================
extern "C" void kernel_launch(void* const* d_in, const int* in_sizes, int n_in,
                              void* d_out, int out_size)
{
    const float* pos1     = (const float*)d_in[0];
    const float* query    = (const float*)d_in[1];
    const float* pos2     = (const float*)d_in[2];
    const float* key_feat = (const float*)d_in[3];
    const float* wq  = (const float*)d_in[4];
    const float* bq  = (const float*)d_in[5];
    const float* wk  = (const float*)d_in[6];
    const float* bk  = (const float*)d_in[7];
    const float* wv  = (const float*)d_in[8];
    const float* bv  = (const float*)d_in[9];
    const float* pw1 = (const float*)d_in[10];
    const float* pb1 = (const float*)d_in[11];
    const float* pg  = (const float*)d_in[12];
    const float* pbt = (const float*)d_in[13];
    const float* pm  = (const float*)d_in[14];
    const float* pv  = (const float*)d_in[15];
    const float* pw2 = (const float*)d_in[16];
    const float* pb2 = (const float*)d_in[17];
    const float* aw1 = (const float*)d_in[18];
    const float* ab1 = (const float*)d_in[19];
    const float* ag  = (const float*)d_in[20];
    const float* abt2= (const float*)d_in[21];
    const float* am  = (const float*)d_in[22];
    const float* av  = (const float*)d_in[23];
    const float* awt = (const float*)d_in[24];
    /* abt (d_in[25]) is constant along the softmax axis -> dropped */
    const float* we  = (const float*)d_in[26];
    const float* be  = (const float*)d_in[27];
    float* out = (float*)d_out;

    static int smem_set = 0;
    if (!smem_set) {
        cudaFuncSetAttribute(attn_gemm_kernel,
            cudaFuncAttributeMaxDynamicSharedMemorySize, SMEM_ATTN);
        smem_set = 1;
    }

    setup_kernel<<<96, 256>>>(aw1, awt, we, ag, av, ab1, am, abt2);
    qkv_kernel<<<dim3(256, NB, 3), 256>>>(query, key_feat, wq, bq, wk, bk, wv, bv);
    knn_kernel<<<dim3(32, NB), 128>>>(pos1, pos2);
    prep_kernel<<<PTOT/2, 128>>>(pos1, pos2, pw1, pb1, pg, pbt, pm, pv, pw2, pb2);
    attn_gemm_kernel<<<MTOT/64, 256, SMEM_ATTN>>>();
    softmax_kernel<<<PTOT/2, 256>>>();
    final_kernel<<<PTOT*2/16, 256>>>(query, be, out);
}

// round 6
// speedup vs baseline: 2.0969x; 1.2318x over previous
#include <cuda_runtime.h>
#include <cuda_bf16.h>
#include <math.h>

#define NB   4
#define NPT  4096
#define NS   4096
#define CIND 128
#define DIMD 64
#define KNNK 20
#define MTOT (NB*NPT*KNNK)   /* 327680 */
#define PTOT (NB*NPT)        /* 16384  */

// ---------------- static device scratch (no runtime allocation) ----------------
__device__ float g_q[PTOT*DIMD];
__device__ float g_k[PTOT*DIMD];
__device__ float g_v[PTOT*DIMD];
__device__ int   g_idx[PTOT*KNNK];
__device__ __nv_bfloat16 g_hh[MTOT*DIMD];   // h hi-plane (bf16)
__device__ __nv_bfloat16 g_hl[MTOT*DIMD];   // h lo-plane (bf16)
__device__ float g_vg[MTOT*DIMD];     // [m][d]
__device__ float g_logits[MTOT*128];  // [m][r*64+o]
__device__ float g_agg[PTOT*2*DIMD];  // [q][d], q = point*2+r
__device__ float g_wet[64*128];       // [d][o2]  transposed we
__device__ float g_abn[512];          // [0:256) inv, [256:512) fused bias
// fragment-ordered, bf16 hi/lo-split weights: uint4 = (b0hi, b1hi, b0lo, b1lo)
__device__ unsigned g_w1f[4*32*32*4];   // [s<4][nfg<32][lane][4]
__device__ unsigned g_w2f[16*16*32*4];  // [s<16][nfg<16][lane][4]

// ---------------- helpers ----------------
__device__ __forceinline__ void mma_bf16(float* d, const unsigned* a, const unsigned* b) {
    asm volatile(
        "mma.sync.aligned.m16n8k16.row.col.f32.bf16.bf16.f32 "
        "{%0,%1,%2,%3}, {%4,%5,%6,%7}, {%8,%9}, {%0,%1,%2,%3};"
        : "+f"(d[0]), "+f"(d[1]), "+f"(d[2]), "+f"(d[3])
        : "r"(a[0]), "r"(a[1]), "r"(a[2]), "r"(a[3]), "r"(b[0]), "r"(b[1]));
}
__device__ __forceinline__ unsigned pack_bf16(float x, float y) {
    __nv_bfloat162 t = __halves2bfloat162(__float2bfloat16(x), __float2bfloat16(y));
    return *(unsigned*)&t;
}
// split helper: returns hi bf16; *lo receives bf16(x - hi)
__device__ __forceinline__ void split_bf16(float x, __nv_bfloat16* hi, __nv_bfloat16* lo) {
    __nv_bfloat16 h = __float2bfloat16(x);
    *hi = h;
    *lo = __float2bfloat16(x - __bfloat162float(h));
}

// ============================================================================
// Setup: bf16 hi/lo split + fragment-order the GEMM weights; fold BN; we^T.
// ============================================================================
__global__ void setup_kernel(const float* __restrict__ aw1, const float* __restrict__ awt,
                             const float* __restrict__ we,  const float* __restrict__ ag,
                             const float* __restrict__ av,  const float* __restrict__ ab1,
                             const float* __restrict__ am,  const float* __restrict__ abt2)
{
    int i0 = blockIdx.x*256 + threadIdx.x;
    int stride = gridDim.x*256;

    // g_w1f: GEMM1 B-frags. B[k][n] = aw1[n*64+k], k<64, n<256. k16 per s.
    for (int i=i0; i<4*32*32; i+=stride) {
        int lane = i & 31, nfg = (i>>5)&31, s = i>>10;
        int gr = lane>>2, tig = lane&3;
        int n = nfg*8 + gr;
        int k0 = s*16 + 2*tig;
        float bk[4] = { aw1[n*64 + k0],     aw1[n*64 + k0+1],
                        aw1[n*64 + k0+8],   aw1[n*64 + k0+9] };
        __nv_bfloat16 hi[4], lo[4];
        #pragma unroll
        for (int j=0;j<4;++j) split_bf16(bk[j], &hi[j], &lo[j]);
        unsigned* dst = &g_w1f[i*4];
        __nv_bfloat162 p;
        p = __halves2bfloat162(hi[0], hi[1]); dst[0] = *(unsigned*)&p;
        p = __halves2bfloat162(hi[2], hi[3]); dst[1] = *(unsigned*)&p;
        p = __halves2bfloat162(lo[0], lo[1]); dst[2] = *(unsigned*)&p;
        p = __halves2bfloat162(lo[2], lo[3]); dst[3] = *(unsigned*)&p;
    }
    // g_w2f: GEMM2 B-frags. B[k][n=o'] = awt[k*128 + (o'&63)*2 + (o'>>6)].
    for (int i=i0; i<16*16*32; i+=stride) {
        int lane = i & 31, nfg = (i>>5)&15, s = i>>9;
        int gr = lane>>2, tig = lane&3;
        int n = nfg*8 + gr;
        int k0 = s*16 + 2*tig;
        int nn = (n&63)*2 + (n>>6);
        float bk[4] = { awt[(k0  )*128 + nn], awt[(k0+1)*128 + nn],
                        awt[(k0+8)*128 + nn], awt[(k0+9)*128 + nn] };
        __nv_bfloat16 hi[4], lo[4];
        #pragma unroll
        for (int j=0;j<4;++j) split_bf16(bk[j], &hi[j], &lo[j]);
        unsigned* dst = &g_w2f[i*4];
        __nv_bfloat162 p;
        p = __halves2bfloat162(hi[0], hi[1]); dst[0] = *(unsigned*)&p;
        p = __halves2bfloat162(hi[2], hi[3]); dst[1] = *(unsigned*)&p;
        p = __halves2bfloat162(lo[0], lo[1]); dst[2] = *(unsigned*)&p;
        p = __halves2bfloat162(lo[2], lo[3]); dst[3] = *(unsigned*)&p;
    }
    for (int i=i0; i<64*128; i+=stride) { int d=i>>7, o2=i&127; g_wet[i] = we[o2*64+d]; }
    for (int i=i0; i<256; i+=stride) {
        float inv = ag[i]*rsqrtf(av[i]+1e-5f);
        g_abn[i]     = inv;
        g_abn[256+i] = (ab1[i]-am[i])*inv + abt2[i];
    }
}

// ============================================================================
// Kernel 1: q/k/v 1x1 conv.
// ============================================================================
__global__ __launch_bounds__(256) void qkv_kernel(
    const float* __restrict__ query, const float* __restrict__ key_feat,
    const float* __restrict__ wq, const float* __restrict__ bq,
    const float* __restrict__ wk, const float* __restrict__ bk,
    const float* __restrict__ wv, const float* __restrict__ bv)
{
    __shared__ float Wsm[64*129];
    __shared__ __align__(16) float xs[128*16];
    int t = threadIdx.x;
    int z = blockIdx.z;
    const float* W    = (z==0)? wq : (z==1)? wk : wv;
    const float* bias = (z==0)? bq : (z==1)? bk : bv;
    const float* inp  = (z==0)? query : key_feat;
    float* outp       = (z==0)? g_q : (z==1)? g_k : g_v;
    int b  = blockIdx.y;
    int n0 = blockIdx.x * 16;

    for (int idx=t; idx<64*128; idx+=256) Wsm[(idx>>7)*129 + (idx&127)] = W[idx];
    for (int idx=t; idx<128*16; idx+=256) {
        int c = idx>>4, i = idx&15;
        xs[c*16+i] = inp[(b*CIND+c)*NPT + n0 + i];
    }
    __syncthreads();

    int d = t & 63, g = t >> 6;
    float bb = bias[d];
    float acc0=bb, acc1=bb, acc2=bb, acc3=bb;
    for (int c=0; c<128; ++c) {
        float w = Wsm[d*129+c];
        float4 v4 = *(const float4*)&xs[c*16 + g*4];
        acc0 += w*v4.x; acc1 += w*v4.y; acc2 += w*v4.z; acc3 += w*v4.w;
    }
    int pb = (b*NPT + n0 + g*4);
    outp[(pb+0)*DIMD + d] = acc0;
    outp[(pb+1)*DIMD + d] = acc1;
    outp[(pb+2)*DIMD + d] = acc2;
    outp[(pb+3)*DIMD + d] = acc3;
}

// ============================================================================
// Kernel 2: KNN (top-20 smallest d = |p1|^2+|p2|^2-2 p1.p2, stable ties).
// ============================================================================
__global__ __launch_bounds__(128) void knn_kernel(
    const float* __restrict__ pos1, const float* __restrict__ pos2)
{
    __shared__ float4 sp[2048];
    int t = threadIdx.x;
    int b = blockIdx.y;
    int n = blockIdx.x*128 + t;
    const float* p1 = pos1 + b*3*NPT;
    float qx = p1[n], qy = p1[NPT+n], qz = p1[2*NPT+n];
    float s1 = qx*qx + qy*qy + qz*qz;

    float bd[KNNK]; int bi[KNNK];
    #pragma unroll
    for (int i=0;i<KNNK;++i) { bd[i]=1e30f; bi[i]=0; }

    const float* p2 = pos2 + b*3*NS;
    for (int ch=0; ch<2; ++ch) {
        __syncthreads();
        for (int j=t; j<2048; j+=128) {
            int jg = ch*2048 + j;
            float x=p2[jg], y=p2[NS+jg], z=p2[2*NS+jg];
            sp[j] = make_float4(x, y, z, x*x+y*y+z*z);
        }
        __syncthreads();
        for (int j=0; j<2048; ++j) {
            float4 p = sp[j];
            float dd = s1 + p.w - 2.0f*(qx*p.x + qy*p.y + qz*p.z);
            if (dd < bd[KNNK-1]) {
                int jg = ch*2048 + j;
                #pragma unroll
                for (int i=KNNK-1; i>=1; --i) {
                    if (dd < bd[i]) {
                        bool sh = dd < bd[i-1];
                        bd[i] = sh ? bd[i-1] : dd;
                        bi[i] = sh ? bi[i-1] : jg;
                    }
                }
                if (dd < bd[0]) { bd[0]=dd; bi[0]=jg; }
            }
        }
    }
    int* op = &g_idx[(b*NPT + n)*KNNK];
    #pragma unroll
    for (int i=0;i<KNNK;++i) op[i] = bi[i];
}

// ============================================================================
// Kernel 3: gather + pos-MLP; h = q - k_g + pe (split to bf16 hi/lo planes);
//           vg = v_g + pe (fp32).
// ============================================================================
__global__ __launch_bounds__(128) void prep_kernel(
    const float* __restrict__ pos1, const float* __restrict__ pos2,
    const float* __restrict__ pw1, const float* __restrict__ pb1,
    const float* __restrict__ pg,  const float* __restrict__ pbt,
    const float* __restrict__ pm,  const float* __restrict__ pvv,
    const float* __restrict__ pw2, const float* __restrict__ pb2)
{
    __shared__ float pw2s[64*65];
    __shared__ __align__(16) float pe1s[2][64*24];
    __shared__ float prel[2][3][KNNK];
    __shared__ float qs[2][64];
    __shared__ int idxs[2][KNNK];
    int t = threadIdx.x;
    int p0 = blockIdx.x*2;

    for (int idx=t; idx<64*64; idx+=128) pw2s[(idx>>6)*65 + (idx&63)] = pw2[idx];
    if (t < 2*KNNK) idxs[t/KNNK][t%KNNK] = g_idx[p0*KNNK + t];
    {
        int pp = t>>6, d = t&63;
        qs[pp][d] = g_q[(p0+pp)*DIMD + d];
    }
    __syncthreads();

    if (t < 2*3*KNNK) {
        int pp = t/(3*KNNK), r = t%(3*KNNK);
        int c = r/KNNK, k = r%KNNK;
        int p = p0+pp, b = p>>12, n = p&4095;
        prel[pp][c][k] = pos1[(b*3+c)*NPT + n] - pos2[(b*3+c)*NS + idxs[pp][k]];
    }
    __syncthreads();

    {   // pe1 = relu(bn(pw1 @ pos_rel + pb1))
        int cH = t & 63, pp = t >> 6;
        float w0 = pw1[cH*3], w1 = pw1[cH*3+1], w2v = pw1[cH*3+2];
        float inv = pg[cH]*rsqrtf(pvv[cH]+1e-5f);
        float tb  = (pb1[cH]-pm[cH])*inv + pbt[cH];
        #pragma unroll
        for (int k=0;k<KNNK;++k) {
            float s = w0*prel[pp][0][k] + w1*prel[pp][1][k] + w2v*prel[pp][2][k];
            pe1s[pp][cH*24+k] = fmaxf(s*inv + tb, 0.0f);
        }
    }
    __syncthreads();

    {   // pe = pw2 @ pe1 + pb2 ; emit h (bf16 hi/lo), vg (fp32)
        int d = t&63, pp = t>>6;
        int p = p0+pp, b = p>>12;
        float acc[KNNK]; float bias = pb2[d];
        #pragma unroll
        for (int k=0;k<KNNK;++k) acc[k]=bias;
        for (int cH=0;cH<64;++cH) {
            float w = pw2s[d*65+cH];
            #pragma unroll
            for (int k4=0;k4<5;++k4) {
                float4 v4 = *(const float4*)&pe1s[pp][cH*24 + k4*4];
                acc[k4*4+0]+=w*v4.x; acc[k4*4+1]+=w*v4.y;
                acc[k4*4+2]+=w*v4.z; acc[k4*4+3]+=w*v4.w;
            }
        }
        float qv = qs[pp][d];
        #pragma unroll
        for (int k=0;k<KNNK;++k) {
            int j = idxs[pp][k];
            int m = p*KNNK + k;
            float kg = g_k[(b*NS+j)*DIMD + d];
            float vv = g_v[(b*NS+j)*DIMD + d];
            float hv = qv - kg + acc[k];
            __nv_bfloat16 hi, lo;
            split_bf16(hv, &hi, &lo);
            g_hh[m*DIMD + d] = hi;
            g_hl[m*DIMD + d] = lo;
            g_vg[m*DIMD + d] = vv + acc[k];
        }
    }
}

// ============================================================================
// Kernel 4 (FUSED, tensor-core): gemm1 + BN/ReLU + gemm2 via 3-product BF16
// mma.m16n8k16. CTA = 64 m-rows, block 256 = 8 warps (mw = w&1, cw = w>>1).
// smem planes (bf16, conflict-free word strides 36 / 132 == 4 mod 32):
//   hstHI/hstLO [64m][64k]   (stride 72 bf16 = 36 words)  2 x 9.2KB
//   astHI/astLO [64m][256k]  (stride 264 bf16 = 132 words) 2 x 33.8KB
// total 86016 B -> 2 CTAs/SM.
// ============================================================================
#define HSTW 36
#define ASTW 132
#define OFF_HHI 0
#define OFF_HLO (64*HSTW)
#define OFF_AHI (2*64*HSTW)
#define OFF_ALO (2*64*HSTW + 64*ASTW)
#define SMEM_ATTN ((2*64*HSTW + 2*64*ASTW)*4)

__global__ __launch_bounds__(256, 2) void attn_gemm_kernel()
{
    extern __shared__ __align__(16) unsigned smu[];
    unsigned* hstHI = smu + OFF_HHI;
    unsigned* hstLO = smu + OFF_HLO;
    unsigned* astHI = smu + OFF_AHI;
    unsigned* astLO = smu + OFF_ALO;
    int t = threadIdx.x;
    int w = t >> 5, lane = t & 31;
    int gr = lane >> 2, tig = lane & 3;
    int mw = w & 1, cw = w >> 1;
    int m0 = blockIdx.x * 64;

    // stage h planes (32 words of 2 bf16 per row)
    {
        const unsigned* hw = (const unsigned*)g_hh;
        const unsigned* lw = (const unsigned*)g_hl;
        for (int idx = t; idx < 64*32; idx += 256) {
            int m = idx >> 5, wk = idx & 31;
            hstHI[m*HSTW + wk] = hw[(m0+m)*32 + wk];
            hstLO[m*HSTW + wk] = lw[(m0+m)*32 + wk];
        }
    }
    __syncthreads();

    // ---------------- phase 1: 64m x 256c, K=64 (4 k16 steps) ----------------
    {
        float acc[2][8][4];
        #pragma unroll
        for (int mf=0;mf<2;++mf)
            #pragma unroll
            for (int nf=0;nf<8;++nf)
                #pragma unroll
                for (int q=0;q<4;++q) acc[mf][nf][q] = 0.f;

        #pragma unroll
        for (int s=0; s<4; ++s) {
            unsigned ahi[2][4], alo[2][4];
            #pragma unroll
            for (int mf=0;mf<2;++mf) {
                int r0 = mw*32 + mf*16 + gr;
                int base = s*8 + tig;
                ahi[mf][0] = hstHI[(r0  )*HSTW + base];
                ahi[mf][1] = hstHI[(r0+8)*HSTW + base];
                ahi[mf][2] = hstHI[(r0  )*HSTW + base + 4];
                ahi[mf][3] = hstHI[(r0+8)*HSTW + base + 4];
                alo[mf][0] = hstLO[(r0  )*HSTW + base];
                alo[mf][1] = hstLO[(r0+8)*HSTW + base];
                alo[mf][2] = hstLO[(r0  )*HSTW + base + 4];
                alo[mf][3] = hstLO[(r0+8)*HSTW + base + 4];
            }
            #pragma unroll
            for (int nf=0;nf<8;++nf) {
                uint4 wf = __ldg((const uint4*)&g_w1f[((s*32 + cw*8 + nf)*32 + lane)*4]);
                unsigned bhi[2] = {wf.x, wf.y};
                unsigned blo[2] = {wf.z, wf.w};
                #pragma unroll
                for (int mf=0;mf<2;++mf) {
                    mma_bf16(acc[mf][nf], ahi[mf], bhi);
                    mma_bf16(acc[mf][nf], ahi[mf], blo);
                    mma_bf16(acc[mf][nf], alo[mf], bhi);
                }
            }
        }

        // epilogue: BN + ReLU -> split to bf16 hi/lo planes
        #pragma unroll
        for (int nf=0;nf<8;++nf) {
            int cb = cw*64 + nf*8 + 2*tig;
            int wd = cw*32 + nf*4 + tig;        // word index (2 bf16 per word)
            float2 iv = __ldg((const float2*)&g_abn[cb]);
            float2 tb = __ldg((const float2*)&g_abn[256+cb]);
            #pragma unroll
            for (int mf=0;mf<2;++mf) {
                int r0 = mw*32 + mf*16 + gr;
                float v0 = fmaxf(fmaf(acc[mf][nf][0], iv.x, tb.x), 0.f);
                float v1 = fmaxf(fmaf(acc[mf][nf][1], iv.y, tb.y), 0.f);
                float v2 = fmaxf(fmaf(acc[mf][nf][2], iv.x, tb.x), 0.f);
                float v3 = fmaxf(fmaf(acc[mf][nf][3], iv.y, tb.y), 0.f);
                __nv_bfloat16 h0,h1,l0,l1;
                split_bf16(v0, &h0, &l0); split_bf16(v1, &h1, &l1);
                __nv_bfloat162 ph = __halves2bfloat162(h0,h1);
                __nv_bfloat162 pl = __halves2bfloat162(l0,l1);
                astHI[(r0  )*ASTW + wd] = *(unsigned*)&ph;
                astLO[(r0  )*ASTW + wd] = *(unsigned*)&pl;
                split_bf16(v2, &h0, &l0); split_bf16(v3, &h1, &l1);
                ph = __halves2bfloat162(h0,h1);
                pl = __halves2bfloat162(l0,l1);
                astHI[(r0+8)*ASTW + wd] = *(unsigned*)&ph;
                astLO[(r0+8)*ASTW + wd] = *(unsigned*)&pl;
            }
        }
    }
    __syncthreads();

    // ---------------- phase 2: 64m x 128o', K=256 (16 k16 steps) ----------------
    {
        float acc[2][4][4];
        #pragma unroll
        for (int mf=0;mf<2;++mf)
            #pragma unroll
            for (int nf=0;nf<4;++nf)
                #pragma unroll
                for (int q=0;q<4;++q) acc[mf][nf][q] = 0.f;

        for (int s=0; s<16; ++s) {
            unsigned ahi[2][4], alo[2][4];
            #pragma unroll
            for (int mf=0;mf<2;++mf) {
                int r0 = mw*32 + mf*16 + gr;
                int base = s*8 + tig;
                ahi[mf][0] = astHI[(r0  )*ASTW + base];
                ahi[mf][1] = astHI[(r0+8)*ASTW + base];
                ahi[mf][2] = astHI[(r0  )*ASTW + base + 4];
                ahi[mf][3] = astHI[(r0+8)*ASTW + base + 4];
                alo[mf][0] = astLO[(r0  )*ASTW + base];
                alo[mf][1] = astLO[(r0+8)*ASTW + base];
                alo[mf][2] = astLO[(r0  )*ASTW + base + 4];
                alo[mf][3] = astLO[(r0+8)*ASTW + base + 4];
            }
            #pragma unroll
            for (int nf=0;nf<4;++nf) {
                uint4 wf = __ldg((const uint4*)&g_w2f[((s*16 + cw*4 + nf)*32 + lane)*4]);
                unsigned bhi[2] = {wf.x, wf.y};
                unsigned blo[2] = {wf.z, wf.w};
                #pragma unroll
                for (int mf=0;mf<2;++mf) {
                    mma_bf16(acc[mf][nf], ahi[mf], bhi);
                    mma_bf16(acc[mf][nf], ahi[mf], blo);
                    mma_bf16(acc[mf][nf], alo[mf], bhi);
                }
            }
        }

        // epilogue: store logits (float2 per fragment row)
        #pragma unroll
        for (int nf=0;nf<4;++nf) {
            int ob = cw*32 + nf*8 + 2*tig;
            #pragma unroll
            for (int mf=0;mf<2;++mf) {
                int r0 = m0 + mw*32 + mf*16 + gr;
                *(float2*)&g_logits[(r0  )*128 + ob] = make_float2(acc[mf][nf][0], acc[mf][nf][1]);
                *(float2*)&g_logits[(r0+8)*128 + ob] = make_float2(acc[mf][nf][2], acc[mf][nf][3]);
            }
        }
    }
}

// ============================================================================
// Kernel 5: softmax over k (=20) + weighted aggregation of vg.
// ============================================================================
__global__ __launch_bounds__(256) void softmax_kernel()
{
    int t = threadIdx.x;
    int p = blockIdx.x*2 + (t>>7);
    int chn = t & 127;          // r*64 + d
    int d = chn & 63;

    const float* lp = &g_logits[p*KNNK*128 + chn];
    float lg[KNNK];
    #pragma unroll
    for (int k=0;k<KNNK;++k) lg[k] = lp[k*128];
    float mx = lg[0];
    #pragma unroll
    for (int k=1;k<KNNK;++k) mx = fmaxf(mx, lg[k]);
    float s = 0.f;
    #pragma unroll
    for (int k=0;k<KNNK;++k) { lg[k] = __expf(lg[k]-mx); s += lg[k]; }
    float inv = 1.f/s;

    const float* vp = &g_vg[p*KNNK*64 + d];
    float acc = 0.f;
    #pragma unroll
    for (int k=0;k<KNNK;++k) acc += lg[k]*vp[k*64];
    g_agg[p*128 + chn] = acc*inv;
}

// ============================================================================
// Kernel 6: final 1x1 conv (DIM->CIN) + residual (nearest-upsampled query).
// ============================================================================
__global__ __launch_bounds__(256) void final_kernel(
    const float* __restrict__ query, const float* __restrict__ be,
    float* __restrict__ out)
{
    __shared__ float wes[64*128];
    __shared__ __align__(16) float aggt[64*16];
    int t = threadIdx.x;
    int q0 = blockIdx.x*16;
    for (int idx=t; idx<64*128; idx+=256) wes[idx] = g_wet[idx];
    for (int idx=t; idx<16*64; idx+=256) {
        int li = idx>>6, d = idx&63;
        aggt[d*16+li] = g_agg[(q0+li)*64 + d];
    }
    __syncthreads();

    int o2 = t & 127, h = t >> 7;
    float acc[8];
    #pragma unroll
    for (int i=0;i<8;++i) acc[i]=0.f;
    for (int d=0; d<64; ++d) {
        float w = wes[d*128+o2];
        float4 a0 = *(const float4*)&aggt[d*16 + h*8];
        float4 a1 = *(const float4*)&aggt[d*16 + h*8 + 4];
        acc[0]+=w*a0.x; acc[1]+=w*a0.y; acc[2]+=w*a0.z; acc[3]+=w*a0.w;
        acc[4]+=w*a1.x; acc[5]+=w*a1.y; acc[6]+=w*a1.z; acc[7]+=w*a1.w;
    }
    float bb = be[o2];
    #pragma unroll
    for (int i=0;i<8;++i) {
        int qq = q0 + h*8 + i;
        int b = qq >> 13, nr = qq & 8191, n = nr >> 1;
        out[b*(128*8192) + o2*8192 + nr] = acc[i] + bb
            + query[b*(128*4096) + o2*4096 + n];
    }
}

// ============================================================================
extern "C" void kernel_launch(void* const* d_in, const int* in_sizes, int n_in,
                              void* d_out, int out_size)
{
    const float* pos1     = (const float*)d_in[0];
    const float* query    = (const float*)d_in[1];
    const float* pos2     = (const float*)d_in[2];
    const float* key_feat = (const float*)d_in[3];
    const float* wq  = (const float*)d_in[4];
    const float* bq  = (const float*)d_in[5];
    const float* wk  = (const float*)d_in[6];
    const float* bk  = (const float*)d_in[7];
    const float* wv  = (const float*)d_in[8];
    const float* bv  = (const float*)d_in[9];
    const float* pw1 = (const float*)d_in[10];
    const float* pb1 = (const float*)d_in[11];
    const float* pg  = (const float*)d_in[12];
    const float* pbt = (const float*)d_in[13];
    const float* pm  = (const float*)d_in[14];
    const float* pv  = (const float*)d_in[15];
    const float* pw2 = (const float*)d_in[16];
    const float* pb2 = (const float*)d_in[17];
    const float* aw1 = (const float*)d_in[18];
    const float* ab1 = (const float*)d_in[19];
    const float* ag  = (const float*)d_in[20];
    const float* abt2= (const float*)d_in[21];
    const float* am  = (const float*)d_in[22];
    const float* av  = (const float*)d_in[23];
    const float* awt = (const float*)d_in[24];
    /* abt (d_in[25]) is constant along the softmax axis -> dropped */
    const float* we  = (const float*)d_in[26];
    const float* be  = (const float*)d_in[27];
    float* out = (float*)d_out;

    static int smem_set = 0;
    if (!smem_set) {
        cudaFuncSetAttribute(attn_gemm_kernel,
            cudaFuncAttributeMaxDynamicSharedMemorySize, SMEM_ATTN);
        smem_set = 1;
    }

    setup_kernel<<<96, 256>>>(aw1, awt, we, ag, av, ab1, am, abt2);
    qkv_kernel<<<dim3(256, NB, 3), 256>>>(query, key_feat, wq, bq, wk, bk, wv, bv);
    knn_kernel<<<dim3(32, NB), 128>>>(pos1, pos2);
    prep_kernel<<<PTOT/2, 128>>>(pos1, pos2, pw1, pb1, pg, pbt, pm, pv, pw2, pb2);
    attn_gemm_kernel<<<MTOT/64, 256, SMEM_ATTN>>>();
    softmax_kernel<<<PTOT/2, 256>>>();
    final_kernel<<<PTOT*2/16, 256>>>(query, be, out);
}

// round 9
// speedup vs baseline: 2.1151x; 1.0087x over previous
#include <cuda_runtime.h>
#include <cuda_bf16.h>
#include <cstdint>
#include <math.h>

#define NB   4
#define NPT  4096
#define NS   4096
#define CIND 128
#define DIMD 64
#define KNNK 20
#define MTOT (NB*NPT*KNNK)   /* 327680 */
#define PTOT (NB*NPT)        /* 16384  */

// ---------------- static device scratch (no runtime allocation) ----------------
__device__ float g_q[PTOT*DIMD];
__device__ float g_k[PTOT*DIMD];
__device__ float g_v[PTOT*DIMD];
__device__ int   g_idx[PTOT*KNNK];
__device__ __nv_bfloat16 g_hh[MTOT*DIMD];   // h hi-plane (bf16)
__device__ __nv_bfloat16 g_hl[MTOT*DIMD];   // h lo-plane (bf16)
__device__ float g_vg[MTOT*DIMD];     // [m][d]
__device__ float g_logits[MTOT*128];  // [m][r*64+o]
__device__ float g_agg[PTOT*2*DIMD];  // [q][d], q = point*2+r
__device__ float g_wet[64*128];       // [d][o2]  transposed we
__device__ float g_abn[512];          // [0:256) inv, [256:512) fused bias
// fragment-ordered, bf16 hi/lo-split weights: uint4 = (b0hi, b1hi, b0lo, b1lo)
__device__ unsigned g_w1f[4*32*32*4];   // [s<4][nfg<32][lane][4]
__device__ unsigned g_w2f[16*16*32*4];  // [s<16][nfg<16][lane][4]

// ---------------- helpers ----------------
__device__ __forceinline__ void mma_bf16(float* d, const unsigned* a, const unsigned* b) {
    asm volatile(
        "mma.sync.aligned.m16n8k16.row.col.f32.bf16.bf16.f32 "
        "{%0,%1,%2,%3}, {%4,%5,%6,%7}, {%8,%9}, {%0,%1,%2,%3};"
        : "+f"(d[0]), "+f"(d[1]), "+f"(d[2]), "+f"(d[3])
        : "r"(a[0]), "r"(a[1]), "r"(a[2]), "r"(a[3]), "r"(b[0]), "r"(b[1]));
}
__device__ __forceinline__ void ldsm_x4(unsigned* r, uint32_t addr) {
    asm volatile("ldmatrix.sync.aligned.m8n8.x4.shared.b16 {%0,%1,%2,%3}, [%4];"
        : "=r"(r[0]), "=r"(r[1]), "=r"(r[2]), "=r"(r[3]) : "r"(addr));
}
__device__ __forceinline__ uint32_t smem_u32(const void* p) {
    uint32_t a;
    asm("{ .reg .u64 t; cvta.to.shared.u64 t, %1; cvt.u32.u64 %0, t; }" : "=r"(a) : "l"(p));
    return a;
}
// split helper: returns hi bf16; *lo receives bf16(x - hi)
__device__ __forceinline__ void split_bf16(float x, __nv_bfloat16* hi, __nv_bfloat16* lo) {
    __nv_bfloat16 h = __float2bfloat16(x);
    *hi = h;
    *lo = __float2bfloat16(x - __bfloat162float(h));
}

// ============================================================================
// Setup: bf16 hi/lo split + fragment-order the GEMM weights; fold BN; we^T.
// ============================================================================
__global__ void setup_kernel(const float* __restrict__ aw1, const float* __restrict__ awt,
                             const float* __restrict__ we,  const float* __restrict__ ag,
                             const float* __restrict__ av,  const float* __restrict__ ab1,
                             const float* __restrict__ am,  const float* __restrict__ abt2)
{
    int i0 = blockIdx.x*256 + threadIdx.x;
    int stride = gridDim.x*256;

    // g_w1f: GEMM1 B-frags. B[k][n] = aw1[n*64+k], k<64, n<256. k16 per s.
    for (int i=i0; i<4*32*32; i+=stride) {
        int lane = i & 31, nfg = (i>>5)&31, s = i>>10;
        int gr = lane>>2, tig = lane&3;
        int n = nfg*8 + gr;
        int k0 = s*16 + 2*tig;
        float bk[4] = { aw1[n*64 + k0],     aw1[n*64 + k0+1],
                        aw1[n*64 + k0+8],   aw1[n*64 + k0+9] };
        __nv_bfloat16 hi[4], lo[4];
        #pragma unroll
        for (int j=0;j<4;++j) split_bf16(bk[j], &hi[j], &lo[j]);
        unsigned* dst = &g_w1f[i*4];
        __nv_bfloat162 p;
        p = __halves2bfloat162(hi[0], hi[1]); dst[0] = *(unsigned*)&p;
        p = __halves2bfloat162(hi[2], hi[3]); dst[1] = *(unsigned*)&p;
        p = __halves2bfloat162(lo[0], lo[1]); dst[2] = *(unsigned*)&p;
        p = __halves2bfloat162(lo[2], lo[3]); dst[3] = *(unsigned*)&p;
    }
    // g_w2f: GEMM2 B-frags. B[k][n=o'] = awt[k*128 + (o'&63)*2 + (o'>>6)].
    for (int i=i0; i<16*16*32; i+=stride) {
        int lane = i & 31, nfg = (i>>5)&15, s = i>>9;
        int gr = lane>>2, tig = lane&3;
        int n = nfg*8 + gr;
        int k0 = s*16 + 2*tig;
        int nn = (n&63)*2 + (n>>6);
        float bk[4] = { awt[(k0  )*128 + nn], awt[(k0+1)*128 + nn],
                        awt[(k0+8)*128 + nn], awt[(k0+9)*128 + nn] };
        __nv_bfloat16 hi[4], lo[4];
        #pragma unroll
        for (int j=0;j<4;++j) split_bf16(bk[j], &hi[j], &lo[j]);
        unsigned* dst = &g_w2f[i*4];
        __nv_bfloat162 p;
        p = __halves2bfloat162(hi[0], hi[1]); dst[0] = *(unsigned*)&p;
        p = __halves2bfloat162(hi[2], hi[3]); dst[1] = *(unsigned*)&p;
        p = __halves2bfloat162(lo[0], lo[1]); dst[2] = *(unsigned*)&p;
        p = __halves2bfloat162(lo[2], lo[3]); dst[3] = *(unsigned*)&p;
    }
    for (int i=i0; i<64*128; i+=stride) { int d=i>>7, o2=i&127; g_wet[i] = we[o2*64+d]; }
    for (int i=i0; i<256; i+=stride) {
        float inv = ag[i]*rsqrtf(av[i]+1e-5f);
        g_abn[i]     = inv;
        g_abn[256+i] = (ab1[i]-am[i])*inv + abt2[i];
    }
}

// ============================================================================
// Kernel 1: q/k/v 1x1 conv.
// ============================================================================
__global__ __launch_bounds__(256) void qkv_kernel(
    const float* __restrict__ query, const float* __restrict__ key_feat,
    const float* __restrict__ wq, const float* __restrict__ bq,
    const float* __restrict__ wk, const float* __restrict__ bk,
    const float* __restrict__ wv, const float* __restrict__ bv)
{
    __shared__ float Wsm[64*129];
    __shared__ __align__(16) float xs[128*16];
    int t = threadIdx.x;
    int z = blockIdx.z;
    const float* W    = (z==0)? wq : (z==1)? wk : wv;
    const float* bias = (z==0)? bq : (z==1)? bk : bv;
    const float* inp  = (z==0)? query : key_feat;
    float* outp       = (z==0)? g_q : (z==1)? g_k : g_v;
    int b  = blockIdx.y;
    int n0 = blockIdx.x * 16;

    for (int idx=t; idx<64*128; idx+=256) Wsm[(idx>>7)*129 + (idx&127)] = W[idx];
    for (int idx=t; idx<128*16; idx+=256) {
        int c = idx>>4, i = idx&15;
        xs[c*16+i] = inp[(b*CIND+c)*NPT + n0 + i];
    }
    __syncthreads();

    int d = t & 63, g = t >> 6;
    float bb = bias[d];
    float acc0=bb, acc1=bb, acc2=bb, acc3=bb;
    for (int c=0; c<128; ++c) {
        float w = Wsm[d*129+c];
        float4 v4 = *(const float4*)&xs[c*16 + g*4];
        acc0 += w*v4.x; acc1 += w*v4.y; acc2 += w*v4.z; acc3 += w*v4.w;
    }
    int pb = (b*NPT + n0 + g*4);
    outp[(pb+0)*DIMD + d] = acc0;
    outp[(pb+1)*DIMD + d] = acc1;
    outp[(pb+2)*DIMD + d] = acc2;
    outp[(pb+3)*DIMD + d] = acc3;
}

// ============================================================================
// Kernel 2: KNN (top-20 smallest d = |p1|^2+|p2|^2-2 p1.p2, stable ties).
// ============================================================================
__global__ __launch_bounds__(128) void knn_kernel(
    const float* __restrict__ pos1, const float* __restrict__ pos2)
{
    __shared__ float4 sp[2048];
    int t = threadIdx.x;
    int b = blockIdx.y;
    int n = blockIdx.x*128 + t;
    const float* p1 = pos1 + b*3*NPT;
    float qx = p1[n], qy = p1[NPT+n], qz = p1[2*NPT+n];
    float s1 = qx*qx + qy*qy + qz*qz;

    float bd[KNNK]; int bi[KNNK];
    #pragma unroll
    for (int i=0;i<KNNK;++i) { bd[i]=1e30f; bi[i]=0; }

    const float* p2 = pos2 + b*3*NS;
    for (int ch=0; ch<2; ++ch) {
        __syncthreads();
        for (int j=t; j<2048; j+=128) {
            int jg = ch*2048 + j;
            float x=p2[jg], y=p2[NS+jg], z=p2[2*NS+jg];
            sp[j] = make_float4(x, y, z, x*x+y*y+z*z);
        }
        __syncthreads();
        for (int j=0; j<2048; ++j) {
            float4 p = sp[j];
            float dd = s1 + p.w - 2.0f*(qx*p.x + qy*p.y + qz*p.z);
            if (dd < bd[KNNK-1]) {
                int jg = ch*2048 + j;
                #pragma unroll
                for (int i=KNNK-1; i>=1; --i) {
                    if (dd < bd[i]) {
                        bool sh = dd < bd[i-1];
                        bd[i] = sh ? bd[i-1] : dd;
                        bi[i] = sh ? bi[i-1] : jg;
                    }
                }
                if (dd < bd[0]) { bd[0]=dd; bi[0]=jg; }
            }
        }
    }
    int* op = &g_idx[(b*NPT + n)*KNNK];
    #pragma unroll
    for (int i=0;i<KNNK;++i) op[i] = bi[i];
}

// ============================================================================
// Kernel 3: gather + pos-MLP; h = q - k_g + pe (bf16 hi/lo planes); vg fp32.
// ============================================================================
__global__ __launch_bounds__(128) void prep_kernel(
    const float* __restrict__ pos1, const float* __restrict__ pos2,
    const float* __restrict__ pw1, const float* __restrict__ pb1,
    const float* __restrict__ pg,  const float* __restrict__ pbt,
    const float* __restrict__ pm,  const float* __restrict__ pvv,
    const float* __restrict__ pw2, const float* __restrict__ pb2)
{
    __shared__ float pw2s[64*65];
    __shared__ __align__(16) float pe1s[2][64*24];
    __shared__ float prel[2][3][KNNK];
    __shared__ float qs[2][64];
    __shared__ int idxs[2][KNNK];
    int t = threadIdx.x;
    int p0 = blockIdx.x*2;

    for (int idx=t; idx<64*64; idx+=128) pw2s[(idx>>6)*65 + (idx&63)] = pw2[idx];
    if (t < 2*KNNK) idxs[t/KNNK][t%KNNK] = g_idx[p0*KNNK + t];
    {
        int pp = t>>6, d = t&63;
        qs[pp][d] = g_q[(p0+pp)*DIMD + d];
    }
    __syncthreads();

    if (t < 2*3*KNNK) {
        int pp = t/(3*KNNK), r = t%(3*KNNK);
        int c = r/KNNK, k = r%KNNK;
        int p = p0+pp, b = p>>12, n = p&4095;
        prel[pp][c][k] = pos1[(b*3+c)*NPT + n] - pos2[(b*3+c)*NS + idxs[pp][k]];
    }
    __syncthreads();

    {
        int cH = t & 63, pp = t >> 6;
        float w0 = pw1[cH*3], w1 = pw1[cH*3+1], w2v = pw1[cH*3+2];
        float inv = pg[cH]*rsqrtf(pvv[cH]+1e-5f);
        float tb  = (pb1[cH]-pm[cH])*inv + pbt[cH];
        #pragma unroll
        for (int k=0;k<KNNK;++k) {
            float s = w0*prel[pp][0][k] + w1*prel[pp][1][k] + w2v*prel[pp][2][k];
            pe1s[pp][cH*24+k] = fmaxf(s*inv + tb, 0.0f);
        }
    }
    __syncthreads();

    {
        int d = t&63, pp = t>>6;
        int p = p0+pp, b = p>>12;
        float acc[KNNK]; float bias = pb2[d];
        #pragma unroll
        for (int k=0;k<KNNK;++k) acc[k]=bias;
        for (int cH=0;cH<64;++cH) {
            float w = pw2s[d*65+cH];
            #pragma unroll
            for (int k4=0;k4<5;++k4) {
                float4 v4 = *(const float4*)&pe1s[pp][cH*24 + k4*4];
                acc[k4*4+0]+=w*v4.x; acc[k4*4+1]+=w*v4.y;
                acc[k4*4+2]+=w*v4.z; acc[k4*4+3]+=w*v4.w;
            }
        }
        float qv = qs[pp][d];
        #pragma unroll
        for (int k=0;k<KNNK;++k) {
            int j = idxs[pp][k];
            int m = p*KNNK + k;
            float kg = g_k[(b*NS+j)*DIMD + d];
            float vv = g_v[(b*NS+j)*DIMD + d];
            float hv = qv - kg + acc[k];
            __nv_bfloat16 hi, lo;
            split_bf16(hv, &hi, &lo);
            g_hh[m*DIMD + d] = hi;
            g_hl[m*DIMD + d] = lo;
            g_vg[m*DIMD + d] = vv + acc[k];
        }
    }
}

// ============================================================================
// Kernel 4 (FUSED, tensor-core): gemm1 + BN/ReLU + gemm2 via 3-product BF16
// mma.m16n8k16, A-fragments via ldmatrix.x4, B LDG.128 batched.
// CTA = 64 m-rows, block 256 = 8 warps (mw = w&1, cw = w>>1).
// smem planes (bf16, word strides 36 / 132 == 4 mod 32 -> LDSM conflict-free):
//   hstHI/hstLO [64m][64k]   (stride 144B)  2 x 9.2KB
//   astHI/astLO [64m][256k]  (stride 528B)  2 x 33.8KB    total 86016 B.
// ============================================================================
#define HSTW 36
#define ASTW 132
#define OFF_HHI 0
#define OFF_HLO (64*HSTW)
#define OFF_AHI (2*64*HSTW)
#define OFF_ALO (2*64*HSTW + 64*ASTW)
#define SMEM_ATTN ((2*64*HSTW + 2*64*ASTW)*4)

__global__ __launch_bounds__(256, 2) void attn_gemm_kernel()
{
    extern __shared__ __align__(16) unsigned smu[];
    unsigned* hstHI = smu + OFF_HHI;
    unsigned* hstLO = smu + OFF_HLO;
    unsigned* astHI = smu + OFF_AHI;
    unsigned* astLO = smu + OFF_ALO;
    int t = threadIdx.x;
    int w = t >> 5, lane = t & 31;
    int gr = lane >> 2, tig = lane & 3;
    int mw = w & 1, cw = w >> 1;
    int m0 = blockIdx.x * 64;

    // ldmatrix lane geometry: matrices (0,1,2,3) = (m0k0, m8k0, m0k8, m8k8)
    int lr  = lane & 7;
    int lm8 = (lane >> 3) & 1;
    int lk8 = (lane >> 4) & 1;

    // stage h planes (32 words of 2 bf16 per row)
    {
        const unsigned* hw = (const unsigned*)g_hh;
        const unsigned* lw = (const unsigned*)g_hl;
        for (int idx = t; idx < 64*32; idx += 256) {
            int m = idx >> 5, wk = idx & 31;
            hstHI[m*HSTW + wk] = hw[(m0+m)*32 + wk];
            hstLO[m*HSTW + wk] = lw[(m0+m)*32 + wk];
        }
    }
    __syncthreads();

    uint32_t hHIb = smem_u32(hstHI), hLOb = smem_u32(hstLO);
    uint32_t aHIb = smem_u32(astHI), aLOb = smem_u32(astLO);

    // ---------------- phase 1: 64m x 256c, K=64 (4 k16 steps) ----------------
    {
        float acc[2][8][4];
        #pragma unroll
        for (int mf=0;mf<2;++mf)
            #pragma unroll
            for (int nf=0;nf<8;++nf)
                #pragma unroll
                for (int q=0;q<4;++q) acc[mf][nf][q] = 0.f;

        uint32_t adH[2], adL[2];
        #pragma unroll
        for (int mf=0;mf<2;++mf) {
            int row = mw*32 + mf*16 + lm8*8 + lr;
            uint32_t off = (uint32_t)row*(HSTW*4) + (uint32_t)lk8*16;
            adH[mf] = hHIb + off;
            adL[mf] = hLOb + off;
        }

        #pragma unroll
        for (int s=0; s<4; ++s) {
            unsigned ahi[2][4], alo[2][4];
            #pragma unroll
            for (int mf=0;mf<2;++mf) {
                ldsm_x4(ahi[mf], adH[mf] + s*32);
                ldsm_x4(alo[mf], adL[mf] + s*32);
            }
            #pragma unroll
            for (int half=0; half<2; ++half) {
                uint4 wf[4];
                #pragma unroll
                for (int j=0;j<4;++j)
                    wf[j] = __ldg((const uint4*)&g_w1f[((s*32 + cw*8 + half*4 + j)*32 + lane)*4]);
                #pragma unroll
                for (int j=0;j<4;++j) {
                    int nf = half*4 + j;
                    unsigned bhi[2] = {wf[j].x, wf[j].y};
                    unsigned blo[2] = {wf[j].z, wf[j].w};
                    #pragma unroll
                    for (int mf=0;mf<2;++mf) {
                        mma_bf16(acc[mf][nf], ahi[mf], bhi);
                        mma_bf16(acc[mf][nf], ahi[mf], blo);
                        mma_bf16(acc[mf][nf], alo[mf], bhi);
                    }
                }
            }
        }

        // epilogue: BN + ReLU -> split to bf16 hi/lo planes
        #pragma unroll
        for (int nf=0;nf<8;++nf) {
            int cb = cw*64 + nf*8 + 2*tig;
            int wd = cw*32 + nf*4 + tig;        // word index (2 bf16 per word)
            float2 iv = __ldg((const float2*)&g_abn[cb]);
            float2 tb = __ldg((const float2*)&g_abn[256+cb]);
            #pragma unroll
            for (int mf=0;mf<2;++mf) {
                int r0 = mw*32 + mf*16 + gr;
                float v0 = fmaxf(fmaf(acc[mf][nf][0], iv.x, tb.x), 0.f);
                float v1 = fmaxf(fmaf(acc[mf][nf][1], iv.y, tb.y), 0.f);
                float v2 = fmaxf(fmaf(acc[mf][nf][2], iv.x, tb.x), 0.f);
                float v3 = fmaxf(fmaf(acc[mf][nf][3], iv.y, tb.y), 0.f);
                __nv_bfloat16 h0,h1,l0,l1;
                split_bf16(v0, &h0, &l0); split_bf16(v1, &h1, &l1);
                __nv_bfloat162 ph = __halves2bfloat162(h0,h1);
                __nv_bfloat162 pl = __halves2bfloat162(l0,l1);
                astHI[(r0  )*ASTW + wd] = *(unsigned*)&ph;
                astLO[(r0  )*ASTW + wd] = *(unsigned*)&pl;
                split_bf16(v2, &h0, &l0); split_bf16(v3, &h1, &l1);
                ph = __halves2bfloat162(h0,h1);
                pl = __halves2bfloat162(l0,l1);
                astHI[(r0+8)*ASTW + wd] = *(unsigned*)&ph;
                astLO[(r0+8)*ASTW + wd] = *(unsigned*)&pl;
            }
        }
    }
    __syncthreads();

    // ---------------- phase 2: 64m x 128o', K=256 (16 k16 steps) ----------------
    {
        float acc[2][4][4];
        #pragma unroll
        for (int mf=0;mf<2;++mf)
            #pragma unroll
            for (int nf=0;nf<4;++nf)
                #pragma unroll
                for (int q=0;q<4;++q) acc[mf][nf][q] = 0.f;

        uint32_t adH[2], adL[2];
        #pragma unroll
        for (int mf=0;mf<2;++mf) {
            int row = mw*32 + mf*16 + lm8*8 + lr;
            uint32_t off = (uint32_t)row*(ASTW*4) + (uint32_t)lk8*16;
            adH[mf] = aHIb + off;
            adL[mf] = aLOb + off;
        }

        #pragma unroll 4
        for (int s=0; s<16; ++s) {
            unsigned ahi[2][4], alo[2][4];
            #pragma unroll
            for (int mf=0;mf<2;++mf) {
                ldsm_x4(ahi[mf], adH[mf] + s*32);
                ldsm_x4(alo[mf], adL[mf] + s*32);
            }
            uint4 wf[4];
            #pragma unroll
            for (int j=0;j<4;++j)
                wf[j] = __ldg((const uint4*)&g_w2f[((s*16 + cw*4 + j)*32 + lane)*4]);
            #pragma unroll
            for (int j=0;j<4;++j) {
                unsigned bhi[2] = {wf[j].x, wf[j].y};
                unsigned blo[2] = {wf[j].z, wf[j].w};
                #pragma unroll
                for (int mf=0;mf<2;++mf) {
                    mma_bf16(acc[mf][j], ahi[mf], bhi);
                    mma_bf16(acc[mf][j], ahi[mf], blo);
                    mma_bf16(acc[mf][j], alo[mf], bhi);
                }
            }
        }

        // epilogue: store logits (float2 per fragment row)
        #pragma unroll
        for (int nf=0;nf<4;++nf) {
            int ob = cw*32 + nf*8 + 2*tig;
            #pragma unroll
            for (int mf=0;mf<2;++mf) {
                int r0 = m0 + mw*32 + mf*16 + gr;
                *(float2*)&g_logits[(r0  )*128 + ob] = make_float2(acc[mf][nf][0], acc[mf][nf][1]);
                *(float2*)&g_logits[(r0+8)*128 + ob] = make_float2(acc[mf][nf][2], acc[mf][nf][3]);
            }
        }
    }
}

// ============================================================================
// Kernel 5: softmax over k (=20) + weighted aggregation of vg.
// ============================================================================
__global__ __launch_bounds__(256) void softmax_kernel()
{
    int t = threadIdx.x;
    int p = blockIdx.x*2 + (t>>7);
    int chn = t & 127;          // r*64 + d
    int d = chn & 63;

    const float* lp = &g_logits[(size_t)p*KNNK*128 + chn];
    float lg[KNNK];
    #pragma unroll
    for (int k=0;k<KNNK;++k) lg[k] = lp[k*128];
    float mx = lg[0];
    #pragma unroll
    for (int k=1;k<KNNK;++k) mx = fmaxf(mx, lg[k]);
    float s = 0.f;
    #pragma unroll
    for (int k=0;k<KNNK;++k) { lg[k] = __expf(lg[k]-mx); s += lg[k]; }
    float inv = 1.f/s;

    const float* vp = &g_vg[(size_t)p*KNNK*64 + d];
    float acc = 0.f;
    #pragma unroll
    for (int k=0;k<KNNK;++k) acc += lg[k]*vp[k*64];
    g_agg[p*128 + chn] = acc*inv;
}

// ============================================================================
// Kernel 6: final 1x1 conv (DIM->CIN) + residual (nearest-upsampled query).
// ============================================================================
__global__ __launch_bounds__(256) void final_kernel(
    const float* __restrict__ query, const float* __restrict__ be,
    float* __restrict__ out)
{
    __shared__ float wes[64*128];
    __shared__ __align__(16) float aggt[64*16];
    int t = threadIdx.x;
    int q0 = blockIdx.x*16;
    for (int idx=t; idx<64*128; idx+=256) wes[idx] = g_wet[idx];
    for (int idx=t; idx<16*64; idx+=256) {
        int li = idx>>6, d = idx&63;
        aggt[d*16+li] = g_agg[(q0+li)*64 + d];
    }
    __syncthreads();

    int o2 = t & 127, h = t >> 7;
    float acc[8];
    #pragma unroll
    for (int i=0;i<8;++i) acc[i]=0.f;
    for (int d=0; d<64; ++d) {
        float w = wes[d*128+o2];
        float4 a0 = *(const float4*)&aggt[d*16 + h*8];
        float4 a1 = *(const float4*)&aggt[d*16 + h*8 + 4];
        acc[0]+=w*a0.x; acc[1]+=w*a0.y; acc[2]+=w*a0.z; acc[3]+=w*a0.w;
        acc[4]+=w*a1.x; acc[5]+=w*a1.y; acc[6]+=w*a1.z; acc[7]+=w*a1.w;
    }
    float bb = be[o2];
    #pragma unroll
    for (int i=0;i<8;++i) {
        int qq = q0 + h*8 + i;
        int b = qq >> 13, nr = qq & 8191, n = nr >> 1;
        out[b*(128*8192) + o2*8192 + nr] = acc[i] + bb
            + query[b*(128*4096) + o2*4096 + n];
    }
}

// ============================================================================
extern "C" void kernel_launch(void* const* d_in, const int* in_sizes, int n_in,
                              void* d_out, int out_size)
{
    const float* pos1     = (const float*)d_in[0];
    const float* query    = (const float*)d_in[1];
    const float* pos2     = (const float*)d_in[2];
    const float* key_feat = (const float*)d_in[3];
    const float* wq  = (const float*)d_in[4];
    const float* bq  = (const float*)d_in[5];
    const float* wk  = (const float*)d_in[6];
    const float* bk  = (const float*)d_in[7];
    const float* wv  = (const float*)d_in[8];
    const float* bv  = (const float*)d_in[9];
    const float* pw1 = (const float*)d_in[10];
    const float* pb1 = (const float*)d_in[11];
    const float* pg  = (const float*)d_in[12];
    const float* pbt = (const float*)d_in[13];
    const float* pm  = (const float*)d_in[14];
    const float* pv  = (const float*)d_in[15];
    const float* pw2 = (const float*)d_in[16];
    const float* pb2 = (const float*)d_in[17];
    const float* aw1 = (const float*)d_in[18];
    const float* ab1 = (const float*)d_in[19];
    const float* ag  = (const float*)d_in[20];
    const float* abt2= (const float*)d_in[21];
    const float* am  = (const float*)d_in[22];
    const float* av  = (const float*)d_in[23];
    const float* awt = (const float*)d_in[24];
    /* abt (d_in[25]) is constant along the softmax axis -> dropped */
    const float* we  = (const float*)d_in[26];
    const float* be  = (const float*)d_in[27];
    float* out = (float*)d_out;

    static int smem_set = 0;
    if (!smem_set) {
        cudaFuncSetAttribute(attn_gemm_kernel,
            cudaFuncAttributeMaxDynamicSharedMemorySize, SMEM_ATTN);
        smem_set = 1;
    }

    setup_kernel<<<96, 256>>>(aw1, awt, we, ag, av, ab1, am, abt2);
    qkv_kernel<<<dim3(256, NB, 3), 256>>>(query, key_feat, wq, bq, wk, bk, wv, bv);
    knn_kernel<<<dim3(32, NB), 128>>>(pos1, pos2);
    prep_kernel<<<PTOT/2, 128>>>(pos1, pos2, pw1, pb1, pg, pbt, pm, pv, pw2, pb2);
    attn_gemm_kernel<<<MTOT/64, 256, SMEM_ATTN>>>();
    softmax_kernel<<<PTOT/2, 256>>>();
    final_kernel<<<PTOT*2/16, 256>>>(query, be, out);
}

// round 10
// speedup vs baseline: 2.3196x; 1.0967x over previous
#include <cuda_runtime.h>
#include <cuda_fp16.h>
#include <cstdint>
#include <math.h>

#define NB   4
#define NPT  4096
#define NS   4096
#define CIND 128
#define DIMD 64
#define KNNK 20
#define MTOT (NB*NPT*KNNK)   /* 327680 */
#define PTOT (NB*NPT)        /* 16384  */

// ---------------- static device scratch (no runtime allocation) ----------------
__device__ float g_q[PTOT*DIMD];
__device__ float g_k[PTOT*DIMD];
__device__ float g_v[PTOT*DIMD];
__device__ int   g_idx[PTOT*KNNK];
__device__ __half g_hh[MTOT*DIMD];    // h (fp16, single plane)
__device__ float g_vg[MTOT*DIMD];     // [m][d]
__device__ float g_logits[MTOT*128];  // [m][r*64+o]
__device__ float g_agg[PTOT*2*DIMD];  // [q][d], q = point*2+r
__device__ float g_wet[64*128];       // [d][o2]  transposed we
__device__ float g_abn[512];          // [0:256) inv, [256:512) fused bias
// fragment-ordered, fp16 hi/lo-split weights: uint4 = (b0hi, b1hi, b0lo, b1lo)
__device__ unsigned g_w1f[4*32*32*4];   // [s<4][nfg<32][lane][4]
__device__ unsigned g_w2f[16*16*32*4];  // [s<16][nfg<16][lane][4]

// ---------------- helpers ----------------
__device__ __forceinline__ void mma_f16(float* d, const unsigned* a, const unsigned* b) {
    asm volatile(
        "mma.sync.aligned.m16n8k16.row.col.f32.f16.f16.f32 "
        "{%0,%1,%2,%3}, {%4,%5,%6,%7}, {%8,%9}, {%0,%1,%2,%3};"
        : "+f"(d[0]), "+f"(d[1]), "+f"(d[2]), "+f"(d[3])
        : "r"(a[0]), "r"(a[1]), "r"(a[2]), "r"(a[3]), "r"(b[0]), "r"(b[1]));
}
__device__ __forceinline__ void ldsm_x4(unsigned* r, uint32_t addr) {
    asm volatile("ldmatrix.sync.aligned.m8n8.x4.shared.b16 {%0,%1,%2,%3}, [%4];"
        : "=r"(r[0]), "=r"(r[1]), "=r"(r[2]), "=r"(r[3]) : "r"(addr));
}
__device__ __forceinline__ uint32_t smem_u32(const void* p) {
    uint32_t a;
    asm("{ .reg .u64 t; cvta.to.shared.u64 t, %1; cvt.u32.u64 %0, t; }" : "=r"(a) : "l"(p));
    return a;
}
// fp16 exact-pair split for weights: b = hi + lo with lo = fp16(b - hi)
__device__ __forceinline__ void split_f16(float x, __half* hi, __half* lo) {
    __half h = __float2half(x);
    *hi = h;
    *lo = __float2half(x - __half2float(h));
}

// ============================================================================
// Setup: fp16 hi/lo split + fragment-order the GEMM weights; fold BN; we^T.
// ============================================================================
__global__ void setup_kernel(const float* __restrict__ aw1, const float* __restrict__ awt,
                             const float* __restrict__ we,  const float* __restrict__ ag,
                             const float* __restrict__ av,  const float* __restrict__ ab1,
                             const float* __restrict__ am,  const float* __restrict__ abt2)
{
    int i0 = blockIdx.x*256 + threadIdx.x;
    int stride = gridDim.x*256;

    // g_w1f: GEMM1 B-frags. B[k][n] = aw1[n*64+k], k<64, n<256. k16 per s.
    for (int i=i0; i<4*32*32; i+=stride) {
        int lane = i & 31, nfg = (i>>5)&31, s = i>>10;
        int gr = lane>>2, tig = lane&3;
        int n = nfg*8 + gr;
        int k0 = s*16 + 2*tig;
        float bk[4] = { aw1[n*64 + k0],     aw1[n*64 + k0+1],
                        aw1[n*64 + k0+8],   aw1[n*64 + k0+9] };
        __half hi[4], lo[4];
        #pragma unroll
        for (int j=0;j<4;++j) split_f16(bk[j], &hi[j], &lo[j]);
        unsigned* dst = &g_w1f[i*4];
        __half2 p;
        p = __halves2half2(hi[0], hi[1]); dst[0] = *(unsigned*)&p;
        p = __halves2half2(hi[2], hi[3]); dst[1] = *(unsigned*)&p;
        p = __halves2half2(lo[0], lo[1]); dst[2] = *(unsigned*)&p;
        p = __halves2half2(lo[2], lo[3]); dst[3] = *(unsigned*)&p;
    }
    // g_w2f: GEMM2 B-frags. B[k][n=o'] = awt[k*128 + (o'&63)*2 + (o'>>6)].
    for (int i=i0; i<16*16*32; i+=stride) {
        int lane = i & 31, nfg = (i>>5)&15, s = i>>9;
        int gr = lane>>2, tig = lane&3;
        int n = nfg*8 + gr;
        int k0 = s*16 + 2*tig;
        int nn = (n&63)*2 + (n>>6);
        float bk[4] = { awt[(k0  )*128 + nn], awt[(k0+1)*128 + nn],
                        awt[(k0+8)*128 + nn], awt[(k0+9)*128 + nn] };
        __half hi[4], lo[4];
        #pragma unroll
        for (int j=0;j<4;++j) split_f16(bk[j], &hi[j], &lo[j]);
        unsigned* dst = &g_w2f[i*4];
        __half2 p;
        p = __halves2half2(hi[0], hi[1]); dst[0] = *(unsigned*)&p;
        p = __halves2half2(hi[2], hi[3]); dst[1] = *(unsigned*)&p;
        p = __halves2half2(lo[0], lo[1]); dst[2] = *(unsigned*)&p;
        p = __halves2half2(lo[2], lo[3]); dst[3] = *(unsigned*)&p;
    }
    for (int i=i0; i<64*128; i+=stride) { int d=i>>7, o2=i&127; g_wet[i] = we[o2*64+d]; }
    for (int i=i0; i<256; i+=stride) {
        float inv = ag[i]*rsqrtf(av[i]+1e-5f);
        g_abn[i]     = inv;
        g_abn[256+i] = (ab1[i]-am[i])*inv + abt2[i];
    }
}

// ============================================================================
// Kernel 1: q/k/v 1x1 conv.
// ============================================================================
__global__ __launch_bounds__(256) void qkv_kernel(
    const float* __restrict__ query, const float* __restrict__ key_feat,
    const float* __restrict__ wq, const float* __restrict__ bq,
    const float* __restrict__ wk, const float* __restrict__ bk,
    const float* __restrict__ wv, const float* __restrict__ bv)
{
    __shared__ float Wsm[64*129];
    __shared__ __align__(16) float xs[128*16];
    int t = threadIdx.x;
    int z = blockIdx.z;
    const float* W    = (z==0)? wq : (z==1)? wk : wv;
    const float* bias = (z==0)? bq : (z==1)? bk : bv;
    const float* inp  = (z==0)? query : key_feat;
    float* outp       = (z==0)? g_q : (z==1)? g_k : g_v;
    int b  = blockIdx.y;
    int n0 = blockIdx.x * 16;

    for (int idx=t; idx<64*128; idx+=256) Wsm[(idx>>7)*129 + (idx&127)] = W[idx];
    for (int idx=t; idx<128*16; idx+=256) {
        int c = idx>>4, i = idx&15;
        xs[c*16+i] = inp[(b*CIND+c)*NPT + n0 + i];
    }
    __syncthreads();

    int d = t & 63, g = t >> 6;
    float bb = bias[d];
    float acc0=bb, acc1=bb, acc2=bb, acc3=bb;
    for (int c=0; c<128; ++c) {
        float w = Wsm[d*129+c];
        float4 v4 = *(const float4*)&xs[c*16 + g*4];
        acc0 += w*v4.x; acc1 += w*v4.y; acc2 += w*v4.z; acc3 += w*v4.w;
    }
    int pb = (b*NPT + n0 + g*4);
    outp[(pb+0)*DIMD + d] = acc0;
    outp[(pb+1)*DIMD + d] = acc1;
    outp[(pb+2)*DIMD + d] = acc2;
    outp[(pb+3)*DIMD + d] = acc3;
}

// ============================================================================
// Kernel 2: KNN (top-20 smallest d = |p1|^2+|p2|^2-2 p1.p2, stable ties).
// ============================================================================
__global__ __launch_bounds__(128) void knn_kernel(
    const float* __restrict__ pos1, const float* __restrict__ pos2)
{
    __shared__ float4 sp[2048];
    int t = threadIdx.x;
    int b = blockIdx.y;
    int n = blockIdx.x*128 + t;
    const float* p1 = pos1 + b*3*NPT;
    float qx = p1[n], qy = p1[NPT+n], qz = p1[2*NPT+n];
    float s1 = qx*qx + qy*qy + qz*qz;

    float bd[KNNK]; int bi[KNNK];
    #pragma unroll
    for (int i=0;i<KNNK;++i) { bd[i]=1e30f; bi[i]=0; }

    const float* p2 = pos2 + b*3*NS;
    for (int ch=0; ch<2; ++ch) {
        __syncthreads();
        for (int j=t; j<2048; j+=128) {
            int jg = ch*2048 + j;
            float x=p2[jg], y=p2[NS+jg], z=p2[2*NS+jg];
            sp[j] = make_float4(x, y, z, x*x+y*y+z*z);
        }
        __syncthreads();
        for (int j=0; j<2048; ++j) {
            float4 p = sp[j];
            float dd = s1 + p.w - 2.0f*(qx*p.x + qy*p.y + qz*p.z);
            if (dd < bd[KNNK-1]) {
                int jg = ch*2048 + j;
                #pragma unroll
                for (int i=KNNK-1; i>=1; --i) {
                    if (dd < bd[i]) {
                        bool sh = dd < bd[i-1];
                        bd[i] = sh ? bd[i-1] : dd;
                        bi[i] = sh ? bi[i-1] : jg;
                    }
                }
                if (dd < bd[0]) { bd[0]=dd; bi[0]=jg; }
            }
        }
    }
    int* op = &g_idx[(b*NPT + n)*KNNK];
    #pragma unroll
    for (int i=0;i<KNNK;++i) op[i] = bi[i];
}

// ============================================================================
// Kernel 3: gather + pos-MLP; h = q - k_g + pe (fp16 plane); vg fp32.
// ============================================================================
__global__ __launch_bounds__(128) void prep_kernel(
    const float* __restrict__ pos1, const float* __restrict__ pos2,
    const float* __restrict__ pw1, const float* __restrict__ pb1,
    const float* __restrict__ pg,  const float* __restrict__ pbt,
    const float* __restrict__ pm,  const float* __restrict__ pvv,
    const float* __restrict__ pw2, const float* __restrict__ pb2)
{
    __shared__ float pw2s[64*65];
    __shared__ __align__(16) float pe1s[2][64*24];
    __shared__ float prel[2][3][KNNK];
    __shared__ float qs[2][64];
    __shared__ int idxs[2][KNNK];
    int t = threadIdx.x;
    int p0 = blockIdx.x*2;

    for (int idx=t; idx<64*64; idx+=128) pw2s[(idx>>6)*65 + (idx&63)] = pw2[idx];
    if (t < 2*KNNK) idxs[t/KNNK][t%KNNK] = g_idx[p0*KNNK + t];
    {
        int pp = t>>6, d = t&63;
        qs[pp][d] = g_q[(p0+pp)*DIMD + d];
    }
    __syncthreads();

    if (t < 2*3*KNNK) {
        int pp = t/(3*KNNK), r = t%(3*KNNK);
        int c = r/KNNK, k = r%KNNK;
        int p = p0+pp, b = p>>12, n = p&4095;
        prel[pp][c][k] = pos1[(b*3+c)*NPT + n] - pos2[(b*3+c)*NS + idxs[pp][k]];
    }
    __syncthreads();

    {
        int cH = t & 63, pp = t >> 6;
        float w0 = pw1[cH*3], w1 = pw1[cH*3+1], w2v = pw1[cH*3+2];
        float inv = pg[cH]*rsqrtf(pvv[cH]+1e-5f);
        float tb  = (pb1[cH]-pm[cH])*inv + pbt[cH];
        #pragma unroll
        for (int k=0;k<KNNK;++k) {
            float s = w0*prel[pp][0][k] + w1*prel[pp][1][k] + w2v*prel[pp][2][k];
            pe1s[pp][cH*24+k] = fmaxf(s*inv + tb, 0.0f);
        }
    }
    __syncthreads();

    {
        int d = t&63, pp = t>>6;
        int p = p0+pp, b = p>>12;
        float acc[KNNK]; float bias = pb2[d];
        #pragma unroll
        for (int k=0;k<KNNK;++k) acc[k]=bias;
        for (int cH=0;cH<64;++cH) {
            float w = pw2s[d*65+cH];
            #pragma unroll
            for (int k4=0;k4<5;++k4) {
                float4 v4 = *(const float4*)&pe1s[pp][cH*24 + k4*4];
                acc[k4*4+0]+=w*v4.x; acc[k4*4+1]+=w*v4.y;
                acc[k4*4+2]+=w*v4.z; acc[k4*4+3]+=w*v4.w;
            }
        }
        float qv = qs[pp][d];
        #pragma unroll
        for (int k=0;k<KNNK;++k) {
            int j = idxs[pp][k];
            int m = p*KNNK + k;
            float kg = g_k[(b*NS+j)*DIMD + d];
            float vv = g_v[(b*NS+j)*DIMD + d];
            float hv = qv - kg + acc[k];
            g_hh[m*DIMD + d] = __float2half(hv);
            g_vg[m*DIMD + d] = vv + acc[k];
        }
    }
}

// ============================================================================
// Kernel 4 (FUSED, tensor-core): gemm1 + BN/ReLU + gemm2 via 2-product FP16
// mma.m16n8k16 (activations single fp16, weights exact fp16 hi+lo pair).
// CTA = 64 m-rows, block 256 = 8 warps (mw = w&1, cw = w>>1).
// smem planes (fp16, word strides 36 / 132 == 4 mod 32 -> LDSM conflict-free):
//   hst [64m][64k]  (stride 144B)  9.2KB
//   ast [64m][256k] (stride 528B)  33.8KB      total 43008 B.
// ============================================================================
#define HSTW 36
#define ASTW 132
#define OFF_HST 0
#define OFF_AST (64*HSTW)
#define SMEM_ATTN ((64*HSTW + 64*ASTW)*4)

__global__ __launch_bounds__(256, 2) void attn_gemm_kernel()
{
    extern __shared__ __align__(16) unsigned smu[];
    unsigned* hst = smu + OFF_HST;
    unsigned* ast = smu + OFF_AST;
    int t = threadIdx.x;
    int w = t >> 5, lane = t & 31;
    int gr = lane >> 2, tig = lane & 3;
    int mw = w & 1, cw = w >> 1;
    int m0 = blockIdx.x * 64;

    // ldmatrix lane geometry: matrices (0,1,2,3) = (m0k0, m8k0, m0k8, m8k8)
    int lr  = lane & 7;
    int lm8 = (lane >> 3) & 1;
    int lk8 = (lane >> 4) & 1;

    // stage h plane (32 words of 2 fp16 per row)
    {
        const unsigned* hw = (const unsigned*)g_hh;
        for (int idx = t; idx < 64*32; idx += 256) {
            int m = idx >> 5, wk = idx & 31;
            hst[m*HSTW + wk] = hw[(m0+m)*32 + wk];
        }
    }
    __syncthreads();

    uint32_t hb = smem_u32(hst);
    uint32_t ab = smem_u32(ast);

    // ---------------- phase 1: 64m x 256c, K=64 (4 k16 steps) ----------------
    {
        float acc[2][8][4];
        #pragma unroll
        for (int mf=0;mf<2;++mf)
            #pragma unroll
            for (int nf=0;nf<8;++nf)
                #pragma unroll
                for (int q=0;q<4;++q) acc[mf][nf][q] = 0.f;

        uint32_t ad[2];
        #pragma unroll
        for (int mf=0;mf<2;++mf) {
            int row = mw*32 + mf*16 + lm8*8 + lr;
            ad[mf] = hb + (uint32_t)row*(HSTW*4) + (uint32_t)lk8*16;
        }

        #pragma unroll
        for (int s=0; s<4; ++s) {
            unsigned av[2][4];
            #pragma unroll
            for (int mf=0;mf<2;++mf) ldsm_x4(av[mf], ad[mf] + s*32);
            #pragma unroll
            for (int half=0; half<2; ++half) {
                uint4 wf[4];
                #pragma unroll
                for (int j=0;j<4;++j)
                    wf[j] = __ldg((const uint4*)&g_w1f[((s*32 + cw*8 + half*4 + j)*32 + lane)*4]);
                #pragma unroll
                for (int j=0;j<4;++j) {
                    int nf = half*4 + j;
                    unsigned bhi[2] = {wf[j].x, wf[j].y};
                    unsigned blo[2] = {wf[j].z, wf[j].w};
                    #pragma unroll
                    for (int mf=0;mf<2;++mf) {
                        mma_f16(acc[mf][nf], av[mf], bhi);
                        mma_f16(acc[mf][nf], av[mf], blo);
                    }
                }
            }
        }

        // epilogue: BN + ReLU -> fp16 plane
        #pragma unroll
        for (int nf=0;nf<8;++nf) {
            int cb = cw*64 + nf*8 + 2*tig;
            int wd = cw*32 + nf*4 + tig;        // word index (2 fp16 per word)
            float2 iv = __ldg((const float2*)&g_abn[cb]);
            float2 tb = __ldg((const float2*)&g_abn[256+cb]);
            #pragma unroll
            for (int mf=0;mf<2;++mf) {
                int r0 = mw*32 + mf*16 + gr;
                float v0 = fmaxf(fmaf(acc[mf][nf][0], iv.x, tb.x), 0.f);
                float v1 = fmaxf(fmaf(acc[mf][nf][1], iv.y, tb.y), 0.f);
                float v2 = fmaxf(fmaf(acc[mf][nf][2], iv.x, tb.x), 0.f);
                float v3 = fmaxf(fmaf(acc[mf][nf][3], iv.y, tb.y), 0.f);
                __half2 p0 = __halves2half2(__float2half(v0), __float2half(v1));
                __half2 p1 = __halves2half2(__float2half(v2), __float2half(v3));
                ast[(r0  )*ASTW + wd] = *(unsigned*)&p0;
                ast[(r0+8)*ASTW + wd] = *(unsigned*)&p1;
            }
        }
    }
    __syncthreads();

    // ---------------- phase 2: 64m x 128o', K=256 (16 k16 steps) ----------------
    {
        float acc[2][4][4];
        #pragma unroll
        for (int mf=0;mf<2;++mf)
            #pragma unroll
            for (int nf=0;nf<4;++nf)
                #pragma unroll
                for (int q=0;q<4;++q) acc[mf][nf][q] = 0.f;

        uint32_t ad[2];
        #pragma unroll
        for (int mf=0;mf<2;++mf) {
            int row = mw*32 + mf*16 + lm8*8 + lr;
            ad[mf] = ab + (uint32_t)row*(ASTW*4) + (uint32_t)lk8*16;
        }

        #pragma unroll 4
        for (int s=0; s<16; ++s) {
            unsigned av[2][4];
            #pragma unroll
            for (int mf=0;mf<2;++mf) ldsm_x4(av[mf], ad[mf] + s*32);
            uint4 wf[4];
            #pragma unroll
            for (int j=0;j<4;++j)
                wf[j] = __ldg((const uint4*)&g_w2f[((s*16 + cw*4 + j)*32 + lane)*4]);
            #pragma unroll
            for (int j=0;j<4;++j) {
                unsigned bhi[2] = {wf[j].x, wf[j].y};
                unsigned blo[2] = {wf[j].z, wf[j].w};
                #pragma unroll
                for (int mf=0;mf<2;++mf) {
                    mma_f16(acc[mf][j], av[mf], bhi);
                    mma_f16(acc[mf][j], av[mf], blo);
                }
            }
        }

        // epilogue: store logits (float2 per fragment row)
        #pragma unroll
        for (int nf=0;nf<4;++nf) {
            int ob = cw*32 + nf*8 + 2*tig;
            #pragma unroll
            for (int mf=0;mf<2;++mf) {
                int r0 = m0 + mw*32 + mf*16 + gr;
                *(float2*)&g_logits[(r0  )*128 + ob] = make_float2(acc[mf][nf][0], acc[mf][nf][1]);
                *(float2*)&g_logits[(r0+8)*128 + ob] = make_float2(acc[mf][nf][2], acc[mf][nf][3]);
            }
        }
    }
}

// ============================================================================
// Kernel 5: softmax over k (=20) + weighted aggregation of vg.
// ============================================================================
__global__ __launch_bounds__(256) void softmax_kernel()
{
    int t = threadIdx.x;
    int p = blockIdx.x*2 + (t>>7);
    int chn = t & 127;          // r*64 + d
    int d = chn & 63;

    const float* lp = &g_logits[(size_t)p*KNNK*128 + chn];
    float lg[KNNK];
    #pragma unroll
    for (int k=0;k<KNNK;++k) lg[k] = lp[k*128];
    float mx = lg[0];
    #pragma unroll
    for (int k=1;k<KNNK;++k) mx = fmaxf(mx, lg[k]);
    float s = 0.f;
    #pragma unroll
    for (int k=0;k<KNNK;++k) { lg[k] = __expf(lg[k]-mx); s += lg[k]; }
    float inv = 1.f/s;

    const float* vp = &g_vg[(size_t)p*KNNK*64 + d];
    float acc = 0.f;
    #pragma unroll
    for (int k=0;k<KNNK;++k) acc += lg[k]*vp[k*64];
    g_agg[p*128 + chn] = acc*inv;
}

// ============================================================================
// Kernel 6: final 1x1 conv (DIM->CIN) + residual (nearest-upsampled query).
// ============================================================================
__global__ __launch_bounds__(256) void final_kernel(
    const float* __restrict__ query, const float* __restrict__ be,
    float* __restrict__ out)
{
    __shared__ float wes[64*128];
    __shared__ __align__(16) float aggt[64*16];
    int t = threadIdx.x;
    int q0 = blockIdx.x*16;
    for (int idx=t; idx<64*128; idx+=256) wes[idx] = g_wet[idx];
    for (int idx=t; idx<16*64; idx+=256) {
        int li = idx>>6, d = idx&63;
        aggt[d*16+li] = g_agg[(q0+li)*64 + d];
    }
    __syncthreads();

    int o2 = t & 127, h = t >> 7;
    float acc[8];
    #pragma unroll
    for (int i=0;i<8;++i) acc[i]=0.f;
    for (int d=0; d<64; ++d) {
        float w = wes[d*128+o2];
        float4 a0 = *(const float4*)&aggt[d*16 + h*8];
        float4 a1 = *(const float4*)&aggt[d*16 + h*8 + 4];
        acc[0]+=w*a0.x; acc[1]+=w*a0.y; acc[2]+=w*a0.z; acc[3]+=w*a0.w;
        acc[4]+=w*a1.x; acc[5]+=w*a1.y; acc[6]+=w*a1.z; acc[7]+=w*a1.w;
    }
    float bb = be[o2];
    #pragma unroll
    for (int i=0;i<8;++i) {
        int qq = q0 + h*8 + i;
        int b = qq >> 13, nr = qq & 8191, n = nr >> 1;
        out[b*(128*8192) + o2*8192 + nr] = acc[i] + bb
            + query[b*(128*4096) + o2*4096 + n];
    }
}

// ============================================================================
extern "C" void kernel_launch(void* const* d_in, const int* in_sizes, int n_in,
                              void* d_out, int out_size)
{
    const float* pos1     = (const float*)d_in[0];
    const float* query    = (const float*)d_in[1];
    const float* pos2     = (const float*)d_in[2];
    const float* key_feat = (const float*)d_in[3];
    const float* wq  = (const float*)d_in[4];
    const float* bq  = (const float*)d_in[5];
    const float* wk  = (const float*)d_in[6];
    const float* bk  = (const float*)d_in[7];
    const float* wv  = (const float*)d_in[8];
    const float* bv  = (const float*)d_in[9];
    const float* pw1 = (const float*)d_in[10];
    const float* pb1 = (const float*)d_in[11];
    const float* pg  = (const float*)d_in[12];
    const float* pbt = (const float*)d_in[13];
    const float* pm  = (const float*)d_in[14];
    const float* pv  = (const float*)d_in[15];
    const float* pw2 = (const float*)d_in[16];
    const float* pb2 = (const float*)d_in[17];
    const float* aw1 = (const float*)d_in[18];
    const float* ab1 = (const float*)d_in[19];
    const float* ag  = (const float*)d_in[20];
    const float* abt2= (const float*)d_in[21];
    const float* am  = (const float*)d_in[22];
    const float* av  = (const float*)d_in[23];
    const float* awt = (const float*)d_in[24];
    /* abt (d_in[25]) is constant along the softmax axis -> dropped */
    const float* we  = (const float*)d_in[26];
    const float* be  = (const float*)d_in[27];
    float* out = (float*)d_out;

    static int smem_set = 0;
    if (!smem_set) {
        cudaFuncSetAttribute(attn_gemm_kernel,
            cudaFuncAttributeMaxDynamicSharedMemorySize, SMEM_ATTN);
        smem_set = 1;
    }

    setup_kernel<<<96, 256>>>(aw1, awt, we, ag, av, ab1, am, abt2);
    qkv_kernel<<<dim3(256, NB, 3), 256>>>(query, key_feat, wq, bq, wk, bk, wv, bv);
    knn_kernel<<<dim3(32, NB), 128>>>(pos1, pos2);
    prep_kernel<<<PTOT/2, 128>>>(pos1, pos2, pw1, pb1, pg, pbt, pm, pv, pw2, pb2);
    attn_gemm_kernel<<<MTOT/64, 256, SMEM_ATTN>>>();
    softmax_kernel<<<PTOT/2, 256>>>();
    final_kernel<<<PTOT*2/16, 256>>>(query, be, out);
}